// round 8
// baseline (speedup 1.0000x reference)
#include <cuda_runtime.h>
#include <cuda_bf16.h>
#include <cstdint>
#include <cstddef>

#define BB 4
#define TT 1024
#define HH 16
#define DD 64
#define CC 1024
#define MM 4096

__device__ float g_V[(size_t)BB * HH * TT * DD];
__device__ float g_O[(size_t)MM * CC];
__device__ int   g_mask_flags;

// fragment-ordered bf16 planes (u32 = packed bf16x2)
__device__ uint32_t g_Ah[(size_t)MM * CC / 2];
__device__ uint32_t g_Al[(size_t)MM * CC / 2];
__device__ uint32_t g_Wh[(size_t)CC * CC / 2];
__device__ uint32_t g_Wl[(size_t)CC * CC / 2];

// Q/K/V attention fragment planes: 64 bh x 8 tiles x 4096 u32
__device__ uint32_t g_Qfh[(size_t)64 * 8 * 4096];
__device__ uint32_t g_Qfl[(size_t)64 * 8 * 4096];
__device__ uint32_t g_Kfh[(size_t)64 * 8 * 4096];
__device__ uint32_t g_Kfl[(size_t)64 * 8 * 4096];
__device__ uint32_t g_Vfh[(size_t)64 * 8 * 4096];
__device__ uint32_t g_Vfl[(size_t)64 * 8 * 4096];

// rpe band-GEMM operands + result
__device__ uint32_t g_RQh[(size_t)64 * 8 * 4096];
__device__ uint32_t g_RQl[(size_t)64 * 8 * 4096];
__device__ uint32_t g_Eh[(size_t)8 * 9 * 4 * 1024];
__device__ uint32_t g_El[(size_t)8 * 9 * 4 * 1024];
__device__ float    g_G[(size_t)64 * 8 * 128 * 1152];

// ===========================================================================
// shared helpers (validated R4-R7)
// ===========================================================================
__device__ __forceinline__ void mma16816(float* c, const uint32_t* a,
                                         const uint32_t* b) {
    asm volatile(
        "mma.sync.aligned.m16n8k16.row.col.f32.bf16.bf16.f32 "
        "{%0,%1,%2,%3}, {%4,%5,%6,%7}, {%8,%9}, {%0,%1,%2,%3};"
        : "+f"(c[0]), "+f"(c[1]), "+f"(c[2]), "+f"(c[3])
        : "r"(a[0]), "r"(a[1]), "r"(a[2]), "r"(a[3]), "r"(b[0]), "r"(b[1]));
}

__device__ __forceinline__ void split2(float x, float y, uint32_t& hi, uint32_t& lo) {
    __nv_bfloat16 hx = __float2bfloat16(x);
    __nv_bfloat16 hy = __float2bfloat16(y);
    __nv_bfloat16 lx = __float2bfloat16(x - __bfloat162float(hx));
    __nv_bfloat16 ly = __float2bfloat16(y - __bfloat162float(hy));
    hi = ((uint32_t)__bfloat16_as_ushort(hy) << 16) | __bfloat16_as_ushort(hx);
    lo = ((uint32_t)__bfloat16_as_ushort(ly) << 16) | __bfloat16_as_ushort(lx);
}

__device__ __forceinline__ int a_slot(int row, int k) {
    const int kstep = k >> 4, kk = k & 15;
    const int mt = row >> 4, rit = row & 15;
    const int lane = ((rit & 7) << 2) | ((kk >> 1) & 3);
    const int r = (rit >> 3) | (((kk >> 3) & 1) << 1);
    return (((kstep << 3) + mt) << 7) + (lane << 2) + r;
}
__device__ __forceinline__ int b_slotN(int n, int k, int NT) {
    const int kstep = k >> 4, kk = k & 15;
    const int nt = n >> 3, gc = n & 7;
    const int lane = (gc << 2) | ((kk >> 1) & 3);
    const int r = (kk >> 3) & 1;
    return (((kstep * NT) + nt) << 6) + (lane << 1) + r;
}

// ===========================================================================
// converters (validated R6/R7 patterns)
// ===========================================================================
__global__ void __launch_bounds__(256) conv_a_kernel(const float* __restrict__ ext,
                                                     int srcsel)
{
    const float* src = srcsel ? g_O : ext;
    const uint32_t o = blockIdx.x * 256 + threadIdx.x;
    const uint32_t region = o >> 10;
    const uint32_t rb = region >> 6, ks = region & 63;
    const uint32_t ol = o & 1023;
    const uint32_t mt = ol >> 7;
    const uint32_t lane = (ol >> 2) & 31;
    const uint32_t r = ol & 3;
    const uint32_t rit = ((r & 1) << 3) | (lane >> 2);
    const uint32_t kk = ((r >> 1) << 3) | ((lane & 3) << 1);
    const uint32_t row = (rb << 7) + (mt << 4) + rit;
    const uint32_t k = (ks << 4) + kk;
    const float2 v = *(const float2*)(src + (size_t)row * 1024 + k);
    uint32_t hi, lo;
    split2(v.x, v.y, hi, lo);
    g_Ah[o] = hi;
    g_Al[o] = lo;
}

__global__ void __launch_bounds__(256) conv_b_kernel(const float* __restrict__ w)
{
    const uint32_t o = blockIdx.x * 256 + threadIdx.x;
    const uint32_t region = o >> 10;
    const uint32_t nb = region >> 6, ks = region & 63;
    const uint32_t ol = o & 1023;
    const uint32_t nt = ol >> 6;
    const uint32_t lane = (ol >> 1) & 31;
    const uint32_t r = ol & 1;
    const uint32_t gc = lane >> 2;
    const uint32_t kk = (r << 3) | ((lane & 3) << 1);
    const uint32_t n = (nb << 7) + (nt << 3) + gc;
    const uint32_t k = (ks << 4) + kk;
    const float2 v = *(const float2*)(w + (size_t)n * 1024 + k);
    uint32_t hi, lo;
    split2(v.x, v.y, hi, lo);
    g_Wh[o] = hi;
    g_Wl[o] = lo;
}

// g_V fp32 head layout -> V fragment planes (B-order NT=8, k=token pairs)
__global__ void __launch_bounds__(256) conv_v_kernel()
{
    const uint32_t o = blockIdx.x * 256 + threadIdx.x;     // 0 .. 2M-1
    const uint32_t region = o >> 12;                       // bh*8 + kt
    const uint32_t bh = region >> 3, kt = region & 7;
    const uint32_t ol = o & 4095;
    const uint32_t ks = ol >> 9;
    const uint32_t nt = (ol >> 6) & 7;
    const uint32_t lane = (ol >> 1) & 31;
    const uint32_t r = ol & 1;
    const uint32_t d = (nt << 3) + (lane >> 2);
    const uint32_t key = (ks << 4) + ((r << 3) | ((lane & 3) << 1));
    const size_t vb = ((size_t)bh * 1024 + (kt << 7) + key) * 64 + d;
    const float v0 = g_V[vb];
    const float v1 = g_V[vb + 64];
    uint32_t hi, lo;
    split2(v0, v1, hi, lo);
    g_Vfh[o] = hi;
    g_Vfl[o] = lo;
}

__global__ void __launch_bounds__(256) conv_rq_kernel(const float* __restrict__ q)
{
    const uint32_t o = blockIdx.x * 256 + threadIdx.x;
    const uint32_t region = o >> 10;
    const uint32_t bhqt = region >> 2, ks = region & 3;
    const uint32_t bh = bhqt >> 3, qt = bhqt & 7;
    const uint32_t b = bh >> 4, h = bh & 15;
    const uint32_t ol = o & 1023;
    const uint32_t mt = ol >> 7;
    const uint32_t lane = (ol >> 2) & 31;
    const uint32_t r = ol & 3;
    const uint32_t rit = ((r & 1) << 3) | (lane >> 2);
    const uint32_t kk = ((r >> 1) << 3) | ((lane & 3) << 1);
    const uint32_t row = (qt << 7) + (mt << 4) + rit;
    const uint32_t k = (ks << 4) + kk;
    const float2 v = *(const float2*)(q + ((size_t)(b * 1024 + row)) * 1024 +
                                      h * 64 + k);
    uint32_t hi, lo;
    split2(v.x, v.y, hi, lo);
    g_RQh[o] = hi;
    g_RQl[o] = lo;
}

__global__ void __launch_bounds__(256) conv_e_kernel(const float* __restrict__ relE)
{
    const uint32_t o = blockIdx.x * 256 + threadIdx.x;
    const uint32_t qt = o / 36864;
    const uint32_t rem = o - qt * 36864;
    const uint32_t region = rem >> 10;
    const uint32_t nb = region >> 2, ks = region & 3;
    const uint32_t ol = rem & 1023;
    const uint32_t nt = ol >> 6;
    const uint32_t lane = (ol >> 1) & 31;
    const uint32_t r = ol & 1;
    const uint32_t gc = lane >> 2;
    const uint32_t kk = (r << 3) | ((lane & 3) << 1);
    const uint32_t n = (nb << 7) + (nt << 3) + gc;
    const uint32_t k = (ks << 4) + kk;
    int j = 872 - (int)(qt << 7) + (int)n;
    j = j < 0 ? 0 : (j > 1998 ? 1998 : j);
    const float2 v = *(const float2*)(relE + (size_t)j * 64 + k);
    uint32_t hi, lo;
    split2(v.x, v.y, hi, lo);
    g_Eh[o] = hi;
    g_El[o] = lo;
}

// ===========================================================================
// fragment-direct projection GEMM.
// dstsel: 0 -> Q fragment planes, 1 -> K fragment planes,
//         2 -> g_V fp32 head layout, 3 -> extDst row-major
// ===========================================================================
__global__ void __launch_bounds__(256, 2) gemm_frag_kernel(
    const float* __restrict__ bias, float* extDst, int dstsel)
{
    const int tid = threadIdx.x;
    const int wid = tid >> 5;
    const int lane = tid & 31;
    const int wm = wid >> 2;
    const int wn = wid & 3;
    const int g = lane >> 2;
    const int tig = lane & 3;
    const int nb = blockIdx.x;
    const int rb = blockIdx.y;

    float acc[4][4][4];
#pragma unroll
    for (int i = 0; i < 4; i++)
#pragma unroll
        for (int j = 0; j < 4; j++)
#pragma unroll
            for (int r = 0; r < 4; r++) acc[i][j][r] = 0.f;

#pragma unroll 1
    for (int ks = 0; ks < 64; ks++) {
        const size_t abase = (size_t)((((rb << 6) + ks) << 3) + (wm << 2)) * 128 +
                             (lane << 2);
        const size_t bbase = (size_t)((((nb << 6) + ks) << 4) + (wn << 2)) * 64 +
                             (lane << 1);
        uint4 ah[4], al[4];
        uint2 bh[4], bl[4];
#pragma unroll
        for (int i = 0; i < 4; i++) {
            ah[i] = *(const uint4*)(g_Ah + abase + (i << 7));
            al[i] = *(const uint4*)(g_Al + abase + (i << 7));
        }
#pragma unroll
        for (int j = 0; j < 4; j++) {
            bh[j] = *(const uint2*)(g_Wh + bbase + (j << 6));
            bl[j] = *(const uint2*)(g_Wl + bbase + (j << 6));
        }
#pragma unroll
        for (int i = 0; i < 4; i++)
#pragma unroll
            for (int j = 0; j < 4; j++) {
                mma16816(acc[i][j], (const uint32_t*)&ah[i], (const uint32_t*)&bh[j]);
                mma16816(acc[i][j], (const uint32_t*)&ah[i], (const uint32_t*)&bl[j]);
                mma16816(acc[i][j], (const uint32_t*)&al[i], (const uint32_t*)&bh[j]);
            }
    }

    const int bm = rb << 7;
    const int bn = nb << 7;
#pragma unroll
    for (int i = 0; i < 4; i++) {
        const int m0 = bm + (wm << 6) + (i << 4) + g;
#pragma unroll
        for (int j = 0; j < 4; j++) {
            const int n = bn + (wn << 5) + (j << 3) + (tig << 1);
            const float2 bv = *(const float2*)(bias + n);
#pragma unroll
            for (int half = 0; half < 2; half++) {
                const int m = m0 + (half << 3);
                float2 o;
                o.x = acc[i][j][half * 2 + 0] + bv.x;
                o.y = acc[i][j][half * 2 + 1] + bv.y;
                if (dstsel <= 1) {
                    const int bh2 = ((m >> 10) << 4) + (n >> 6);
                    const int tile = (m >> 7) & 7;
                    const int row = m & 127;
                    const int d = n & 63;
                    uint32_t hi, lo;
                    split2(o.x, o.y, hi, lo);
                    const size_t base = ((size_t)((bh2 << 3) + tile)) << 12;
                    if (dstsel == 0) {
                        const size_t s = base + a_slot(row, d);
                        g_Qfh[s] = hi; g_Qfl[s] = lo;
                    } else {
                        const size_t s = base + b_slotN(row, d, 16);
                        g_Kfh[s] = hi; g_Kfl[s] = lo;
                    }
                } else if (dstsel == 2) {
                    const size_t idx = (((size_t)((m >> 10) * 16 + (n >> 6)) * 1024 +
                                        (size_t)(m & 1023)) << 6) + (n & 63);
                    *(float2*)(g_V + idx) = o;
                } else {
                    *(float2*)(extDst + (size_t)m * 1024 + n) = o;
                }
            }
        }
    }
}

// ===========================================================================
// G band GEMM (validated R7, unchanged)
// ===========================================================================
__global__ void __launch_bounds__(256, 2) g_gemm_kernel()
{
    const int tid = threadIdx.x;
    const int wid = tid >> 5;
    const int lane = tid & 31;
    const int wm = wid >> 2;
    const int wn = wid & 3;
    const int g = lane >> 2;
    const int tig = lane & 3;
    const int nb = blockIdx.x;
    const int qt = blockIdx.y;
    const int bh = blockIdx.z;

    float acc[4][4][4];
#pragma unroll
    for (int i = 0; i < 4; i++)
#pragma unroll
        for (int j = 0; j < 4; j++)
#pragma unroll
            for (int r = 0; r < 4; r++) acc[i][j][r] = 0.f;

#pragma unroll
    for (int ks = 0; ks < 4; ks++) {
        const size_t abase = (size_t)(((((bh << 3) + qt) << 2) + ks) * 8 +
                                      (wm << 2)) * 128 + (lane << 2);
        const size_t bbase = (size_t)((((qt * 9 + nb) << 2) + ks) * 16 +
                                      (wn << 2)) * 64 + (lane << 1);
        uint4 ah[4], al[4];
        uint2 bh2[4], bl2[4];
#pragma unroll
        for (int i = 0; i < 4; i++) {
            ah[i] = *(const uint4*)(g_RQh + abase + (i << 7));
            al[i] = *(const uint4*)(g_RQl + abase + (i << 7));
        }
#pragma unroll
        for (int j = 0; j < 4; j++) {
            bh2[j] = *(const uint2*)(g_Eh + bbase + (j << 6));
            bl2[j] = *(const uint2*)(g_El + bbase + (j << 6));
        }
#pragma unroll
        for (int i = 0; i < 4; i++)
#pragma unroll
            for (int j = 0; j < 4; j++) {
                mma16816(acc[i][j], (const uint32_t*)&ah[i], (const uint32_t*)&bh2[j]);
                mma16816(acc[i][j], (const uint32_t*)&ah[i], (const uint32_t*)&bl2[j]);
                mma16816(acc[i][j], (const uint32_t*)&al[i], (const uint32_t*)&bh2[j]);
            }
    }

    float* Gb = g_G + (size_t)(((bh << 3) + qt) << 7) * 1152;
#pragma unroll
    for (int i = 0; i < 4; i++) {
        const int m0 = (wm << 6) + (i << 4) + g;
#pragma unroll
        for (int j = 0; j < 4; j++) {
            const int n = (nb << 7) + (wn << 5) + (j << 3) + (tig << 1);
#pragma unroll
            for (int half = 0; half < 2; half++) {
                const int m = m0 + (half << 3);
                *(float2*)(Gb + (size_t)m * 1152 + n) =
                    make_float2(acc[i][j][half * 2 + 0], acc[i][j][half * 2 + 1]);
            }
        }
    }
}

// ===========================================================================
// mask dtype-width detector (validated)
// ===========================================================================
__global__ void mask_detect_kernel(const unsigned int* __restrict__ m) {
    unsigned f = 0;
    for (unsigned i = blockIdx.x * blockDim.x + threadIdx.x; i < (1u << 20);
         i += blockDim.x * gridDim.x) {
        unsigned w = m[i];
        if (w == 0u) continue;
        unsigned lo = w & 0xFFFFu;
        if (lo == 0x3F80u || lo == 0x3C00u) f |= 1u;
        if (((w & 0xFEFEFEFEu) == 0u) && w > 1u) f |= 2u;
    }
    if (f) atomicOr(&g_mask_flags, (int)f);
}

// ===========================================================================
// flash attention: S=QK^T (mma) + G + mask -> online softmax -> P.V (mma)
// grid (qt=8, bh=64), 8 warps, warp owns 16 q-rows. No SMEM.
// ===========================================================================
__global__ void __launch_bounds__(256) flash_kernel(const void* __restrict__ mask)
{
    const int tid = threadIdx.x;
    const int wid = tid >> 5;
    const int lane = tid & 31;
    const int g = lane >> 2;
    const int tig = lane & 3;
    const int qt = blockIdx.x;
    const int bh = blockIdx.y;
    const int b = bh >> 4, h = bh & 15;

    uint4 qh[4], ql[4];
    {
        const size_t qbase = ((size_t)((bh << 3) + qt)) << 12;
#pragma unroll
        for (int s = 0; s < 4; s++) {
            const size_t ai = qbase + (((s << 3) + wid) << 7) + (lane << 2);
            qh[s] = *(const uint4*)(g_Qfh + ai);
            ql[s] = *(const uint4*)(g_Qfl + ai);
        }
    }

    const int qi0 = (wid << 4) + g;
    const float* Gr0 = g_G + ((size_t)(((bh << 3) + qt) << 7) + qi0) * 1152 +
                       (127 - qi0);
    const float* Gr1 = Gr0 + 8 * 1152 - 8;

    const int fl = g_mask_flags;
    const int wdt = (fl & 1) ? 2 : ((fl & 2) ? 1 : 4);
    const size_t mrow0 = ((size_t)(b << 10) + (qt << 7) + qi0) << 10;
    const size_t mrow1 = mrow0 + (8 << 10);

    const float NEG = __int_as_float(0xff800000);
    float m0 = NEG, m1 = NEG, l0 = 0.f, l1 = 0.f;
    float o[8][4];
#pragma unroll
    for (int j = 0; j < 8; j++)
#pragma unroll
        for (int r = 0; r < 4; r++) o[j][r] = 0.f;

#pragma unroll 1
    for (int kt = 0; kt < 8; kt++) {
        const size_t kbase = ((size_t)((bh << 3) + kt)) << 12;
        float acc[16][4];
#pragma unroll
        for (int j = 0; j < 16; j++)
#pragma unroll
            for (int r = 0; r < 4; r++) acc[j][r] = 0.f;

#pragma unroll
        for (int j = 0; j < 16; j++) {
#pragma unroll
            for (int s = 0; s < 4; s++) {
                const size_t bi = kbase + (((s << 4) + j) << 6) + (lane << 1);
                uint2 kh2 = *(const uint2*)(g_Kfh + bi);
                uint2 kl2 = *(const uint2*)(g_Kfl + bi);
                mma16816(acc[j], (const uint32_t*)&qh[s], (const uint32_t*)&kh2);
                mma16816(acc[j], (const uint32_t*)&qh[s], (const uint32_t*)&kl2);
                mma16816(acc[j], (const uint32_t*)&ql[s], (const uint32_t*)&kh2);
            }
        }

        // add G, scale by 8, mask; track chunk row max
        const int kc = (kt << 7) + (tig << 1);
        float cm0 = NEG, cm1 = NEG;
#pragma unroll
        for (int j = 0; j < 16; j++) {
            const int k = kc + (j << 3);
            float s00 = (acc[j][0] + Gr0[k]) * 8.f;
            float s01 = (acc[j][1] + Gr0[k + 1]) * 8.f;
            float s10 = (acc[j][2] + Gr1[k]) * 8.f;
            float s11 = (acc[j][3] + Gr1[k + 1]) * 8.f;
            if (wdt == 4) {
                const unsigned int* mp = (const unsigned int*)mask;
                if (mp[mrow0 + k]) s00 = NEG;
                if (mp[mrow0 + k + 1]) s01 = NEG;
                if (mp[mrow1 + k]) s10 = NEG;
                if (mp[mrow1 + k + 1]) s11 = NEG;
            } else if (wdt == 2) {
                const unsigned short* mp = (const unsigned short*)mask;
                if (mp[mrow0 + k]) s00 = NEG;
                if (mp[mrow0 + k + 1]) s01 = NEG;
                if (mp[mrow1 + k]) s10 = NEG;
                if (mp[mrow1 + k + 1]) s11 = NEG;
            } else {
                const unsigned char* mp = (const unsigned char*)mask;
                if (mp[mrow0 + k]) s00 = NEG;
                if (mp[mrow0 + k + 1]) s01 = NEG;
                if (mp[mrow1 + k]) s10 = NEG;
                if (mp[mrow1 + k + 1]) s11 = NEG;
            }
            acc[j][0] = s00; acc[j][1] = s01; acc[j][2] = s10; acc[j][3] = s11;
            cm0 = fmaxf(cm0, fmaxf(s00, s01));
            cm1 = fmaxf(cm1, fmaxf(s10, s11));
        }
        cm0 = fmaxf(cm0, __shfl_xor_sync(0xffffffffu, cm0, 1));
        cm0 = fmaxf(cm0, __shfl_xor_sync(0xffffffffu, cm0, 2));
        cm1 = fmaxf(cm1, __shfl_xor_sync(0xffffffffu, cm1, 1));
        cm1 = fmaxf(cm1, __shfl_xor_sync(0xffffffffu, cm1, 2));

        const float nm0 = fmaxf(m0, cm0);
        const float nm1 = fmaxf(m1, cm1);
        const float a0 = expf(m0 - nm0);
        const float a1 = expf(m1 - nm1);
        m0 = nm0; m1 = nm1;

        float sum0 = 0.f, sum1 = 0.f;
#pragma unroll
        for (int j = 0; j < 16; j++) {
            acc[j][0] = expf(acc[j][0] - nm0);
            acc[j][1] = expf(acc[j][1] - nm0);
            acc[j][2] = expf(acc[j][2] - nm1);
            acc[j][3] = expf(acc[j][3] - nm1);
            sum0 += acc[j][0] + acc[j][1];
            sum1 += acc[j][2] + acc[j][3];
        }
        sum0 += __shfl_xor_sync(0xffffffffu, sum0, 1);
        sum0 += __shfl_xor_sync(0xffffffffu, sum0, 2);
        sum1 += __shfl_xor_sync(0xffffffffu, sum1, 1);
        sum1 += __shfl_xor_sync(0xffffffffu, sum1, 2);
        l0 = l0 * a0 + sum0;
        l1 = l1 * a1 + sum1;

#pragma unroll
        for (int j = 0; j < 8; j++) {
            o[j][0] *= a0; o[j][1] *= a0;
            o[j][2] *= a1; o[j][3] *= a1;
        }

        // P.V: convert P fragments in-register (C-frag pairs == A-frag k-pairs)
#pragma unroll
        for (int s2 = 0; s2 < 8; s2++) {
            uint32_t ph[4], pl[4];
            split2(acc[2 * s2][0], acc[2 * s2][1], ph[0], pl[0]);
            split2(acc[2 * s2][2], acc[2 * s2][3], ph[1], pl[1]);
            split2(acc[2 * s2 + 1][0], acc[2 * s2 + 1][1], ph[2], pl[2]);
            split2(acc[2 * s2 + 1][2], acc[2 * s2 + 1][3], ph[3], pl[3]);
#pragma unroll
            for (int j2 = 0; j2 < 8; j2++) {
                const size_t bi = kbase + (((s2 << 3) + j2) << 6) + (lane << 1);
                uint2 vh2 = *(const uint2*)(g_Vfh + bi);
                uint2 vl2 = *(const uint2*)(g_Vfl + bi);
                mma16816(o[j2], ph, (const uint32_t*)&vh2);
                mma16816(o[j2], ph, (const uint32_t*)&vl2);
                mma16816(o[j2], pl, (const uint32_t*)&vh2);
            }
        }
    }

    const float inv0 = 1.f / l0;
    const float inv1 = 1.f / l1;
    const int qrow = (qt << 7) + qi0;
#pragma unroll
    for (int j2 = 0; j2 < 8; j2++) {
        const int d = (j2 << 3) + (tig << 1);
        float* op = g_O + ((size_t)(b * 1024 + qrow)) * 1024 + h * 64 + d;
        *(float2*)op = make_float2(o[j2][0] * inv0, o[j2][1] * inv0);
        *(float2*)(op + (size_t)8 * 1024) = make_float2(o[j2][2] * inv1,
                                                        o[j2][3] * inv1);
    }
}

// ===========================================================================
// Launch
// ===========================================================================
extern "C" void kernel_launch(void* const* d_in, const int* in_sizes, int n_in,
                              void* d_out, int out_size)
{
    const float* query = (const float*)d_in[0];
    const float* key_i = (const float*)d_in[1];
    const float* value = (const float*)d_in[2];
    const void*  mask  = d_in[3];
    const float* q_w = (const float*)d_in[4];
    const float* q_b = (const float*)d_in[5];
    const float* k_w = (const float*)d_in[6];
    const float* k_b = (const float*)d_in[7];
    const float* v_w = (const float*)d_in[8];
    const float* v_b = (const float*)d_in[9];
    const float* o_w = (const float*)d_in[10];
    const float* o_b = (const float*)d_in[11];
    const float* relE = (const float*)d_in[12];
    float* out = (float*)d_out;

    dim3 gf(8, 32);

    conv_a_kernel<<<8192, 256>>>(query, 0);
    conv_b_kernel<<<2048, 256>>>(q_w);
    gemm_frag_kernel<<<gf, 256>>>(q_b, nullptr, 0);

    conv_a_kernel<<<8192, 256>>>(key_i, 0);
    conv_b_kernel<<<2048, 256>>>(k_w);
    gemm_frag_kernel<<<gf, 256>>>(k_b, nullptr, 1);

    conv_a_kernel<<<8192, 256>>>(value, 0);
    conv_b_kernel<<<2048, 256>>>(v_w);
    gemm_frag_kernel<<<gf, 256>>>(v_b, nullptr, 2);
    conv_v_kernel<<<8192, 256>>>();

    conv_rq_kernel<<<8192, 256>>>(query);
    conv_e_kernel<<<1152, 256>>>(relE);
    g_gemm_kernel<<<dim3(9, 8, 64), 256>>>();

    mask_detect_kernel<<<256, 256>>>((const unsigned int*)mask);

    flash_kernel<<<dim3(8, 64), 256>>>(mask);

    conv_a_kernel<<<8192, 256>>>(g_O, 1);
    conv_b_kernel<<<2048, 256>>>(o_w);
    gemm_frag_kernel<<<gf, 256>>>(o_b, out, 3);
}

// round 9
// speedup vs baseline: 1.5784x; 1.5784x over previous
#include <cuda_runtime.h>
#include <cuda_bf16.h>
#include <cstdint>
#include <cstddef>

#define BB 4
#define TT 1024
#define HH 16
#define DD 64
#define CC 1024
#define MM 4096

__device__ float g_V[(size_t)BB * HH * TT * DD];
__device__ float g_S[(size_t)BB * HH * TT * TT];
__device__ float g_O[(size_t)MM * CC];
__device__ int   g_mask_flags;

// fragment-ordered bf16 planes (u32 = packed bf16x2)
__device__ uint32_t g_Ah[(size_t)MM * CC / 2];
__device__ uint32_t g_Al[(size_t)MM * CC / 2];
__device__ uint32_t g_Wh[(size_t)CC * CC / 2];
__device__ uint32_t g_Wl[(size_t)CC * CC / 2];

// Q/K/V attention fragment planes: 64 bh x 8 tiles x 4096 u32
__device__ uint32_t g_Qfh[(size_t)64 * 8 * 4096];
__device__ uint32_t g_Qfl[(size_t)64 * 8 * 4096];
__device__ uint32_t g_Kfh[(size_t)64 * 8 * 4096];
__device__ uint32_t g_Kfl[(size_t)64 * 8 * 4096];
__device__ uint32_t g_Vfh[(size_t)64 * 8 * 4096];
__device__ uint32_t g_Vfl[(size_t)64 * 8 * 4096];

// P fragment planes: 64 bh x 8 qt x 8 kc x 8192 u32
__device__ uint32_t g_Pfh[(size_t)4096 * 8192];
__device__ uint32_t g_Pfl[(size_t)4096 * 8192];

// rpe band-GEMM operands + result
__device__ uint32_t g_RQh[(size_t)64 * 8 * 4096];
__device__ uint32_t g_RQl[(size_t)64 * 8 * 4096];
__device__ uint32_t g_Eh[(size_t)8 * 9 * 4 * 1024];
__device__ uint32_t g_El[(size_t)8 * 9 * 4 * 1024];
__device__ float    g_G[(size_t)64 * 8 * 128 * 1152];

// ===========================================================================
// shared helpers (validated R4-R8)
// ===========================================================================
__device__ __forceinline__ void mma16816(float* c, const uint32_t* a,
                                         const uint32_t* b) {
    asm volatile(
        "mma.sync.aligned.m16n8k16.row.col.f32.bf16.bf16.f32 "
        "{%0,%1,%2,%3}, {%4,%5,%6,%7}, {%8,%9}, {%0,%1,%2,%3};"
        : "+f"(c[0]), "+f"(c[1]), "+f"(c[2]), "+f"(c[3])
        : "r"(a[0]), "r"(a[1]), "r"(a[2]), "r"(a[3]), "r"(b[0]), "r"(b[1]));
}

__device__ __forceinline__ void split2(float x, float y, uint32_t& hi, uint32_t& lo) {
    __nv_bfloat16 hx = __float2bfloat16(x);
    __nv_bfloat16 hy = __float2bfloat16(y);
    __nv_bfloat16 lx = __float2bfloat16(x - __bfloat162float(hx));
    __nv_bfloat16 ly = __float2bfloat16(y - __bfloat162float(hy));
    hi = ((uint32_t)__bfloat16_as_ushort(hy) << 16) | __bfloat16_as_ushort(hx);
    lo = ((uint32_t)__bfloat16_as_ushort(ly) << 16) | __bfloat16_as_ushort(lx);
}

__device__ __forceinline__ int a_slot(int row, int k) {
    const int kstep = k >> 4, kk = k & 15;
    const int mt = row >> 4, rit = row & 15;
    const int lane = ((rit & 7) << 2) | ((kk >> 1) & 3);
    const int r = (rit >> 3) | (((kk >> 3) & 1) << 1);
    return (((kstep << 3) + mt) << 7) + (lane << 2) + r;
}
__device__ __forceinline__ int b_slotN(int n, int k, int NT) {
    const int kstep = k >> 4, kk = k & 15;
    const int nt = n >> 3, gc = n & 7;
    const int lane = (gc << 2) | ((kk >> 1) & 3);
    const int r = (kk >> 3) & 1;
    return (((kstep * NT) + nt) << 6) + (lane << 1) + r;
}

// ===========================================================================
// converters (validated)
// ===========================================================================
__global__ void __launch_bounds__(256) conv_a_kernel(const float* __restrict__ ext,
                                                     int srcsel)
{
    const float* src = srcsel ? g_O : ext;
    const uint32_t o = blockIdx.x * 256 + threadIdx.x;
    const uint32_t region = o >> 10;
    const uint32_t rb = region >> 6, ks = region & 63;
    const uint32_t ol = o & 1023;
    const uint32_t mt = ol >> 7;
    const uint32_t lane = (ol >> 2) & 31;
    const uint32_t r = ol & 3;
    const uint32_t rit = ((r & 1) << 3) | (lane >> 2);
    const uint32_t kk = ((r >> 1) << 3) | ((lane & 3) << 1);
    const uint32_t row = (rb << 7) + (mt << 4) + rit;
    const uint32_t k = (ks << 4) + kk;
    const float2 v = *(const float2*)(src + (size_t)row * 1024 + k);
    uint32_t hi, lo;
    split2(v.x, v.y, hi, lo);
    g_Ah[o] = hi;
    g_Al[o] = lo;
}

__global__ void __launch_bounds__(256) conv_b_kernel(const float* __restrict__ w)
{
    const uint32_t o = blockIdx.x * 256 + threadIdx.x;
    const uint32_t region = o >> 10;
    const uint32_t nb = region >> 6, ks = region & 63;
    const uint32_t ol = o & 1023;
    const uint32_t nt = ol >> 6;
    const uint32_t lane = (ol >> 1) & 31;
    const uint32_t r = ol & 1;
    const uint32_t gc = lane >> 2;
    const uint32_t kk = (r << 3) | ((lane & 3) << 1);
    const uint32_t n = (nb << 7) + (nt << 3) + gc;
    const uint32_t k = (ks << 4) + kk;
    const float2 v = *(const float2*)(w + (size_t)n * 1024 + k);
    uint32_t hi, lo;
    split2(v.x, v.y, hi, lo);
    g_Wh[o] = hi;
    g_Wl[o] = lo;
}

// g_V fp32 head layout -> V fragment planes (validated R8)
__global__ void __launch_bounds__(256) conv_v_kernel()
{
    const uint32_t o = blockIdx.x * 256 + threadIdx.x;
    const uint32_t region = o >> 12;
    const uint32_t bh = region >> 3, kt = region & 7;
    const uint32_t ol = o & 4095;
    const uint32_t ks = ol >> 9;
    const uint32_t nt = (ol >> 6) & 7;
    const uint32_t lane = (ol >> 1) & 31;
    const uint32_t r = ol & 1;
    const uint32_t d = (nt << 3) + (lane >> 2);
    const uint32_t key = (ks << 4) + ((r << 3) | ((lane & 3) << 1));
    const size_t vb = ((size_t)bh * 1024 + (kt << 7) + key) * 64 + d;
    const float v0 = g_V[vb];
    const float v1 = g_V[vb + 64];
    uint32_t hi, lo;
    split2(v0, v1, hi, lo);
    g_Vfh[o] = hi;
    g_Vfl[o] = lo;
}

__global__ void __launch_bounds__(256) conv_rq_kernel(const float* __restrict__ q)
{
    const uint32_t o = blockIdx.x * 256 + threadIdx.x;
    const uint32_t region = o >> 10;
    const uint32_t bhqt = region >> 2, ks = region & 3;
    const uint32_t bh = bhqt >> 3, qt = bhqt & 7;
    const uint32_t b = bh >> 4, h = bh & 15;
    const uint32_t ol = o & 1023;
    const uint32_t mt = ol >> 7;
    const uint32_t lane = (ol >> 2) & 31;
    const uint32_t r = ol & 3;
    const uint32_t rit = ((r & 1) << 3) | (lane >> 2);
    const uint32_t kk = ((r >> 1) << 3) | ((lane & 3) << 1);
    const uint32_t row = (qt << 7) + (mt << 4) + rit;
    const uint32_t k = (ks << 4) + kk;
    const float2 v = *(const float2*)(q + ((size_t)(b * 1024 + row)) * 1024 +
                                      h * 64 + k);
    uint32_t hi, lo;
    split2(v.x, v.y, hi, lo);
    g_RQh[o] = hi;
    g_RQl[o] = lo;
}

__global__ void __launch_bounds__(256) conv_e_kernel(const float* __restrict__ relE)
{
    const uint32_t o = blockIdx.x * 256 + threadIdx.x;
    const uint32_t qt = o / 36864;
    const uint32_t rem = o - qt * 36864;
    const uint32_t region = rem >> 10;
    const uint32_t nb = region >> 2, ks = region & 3;
    const uint32_t ol = rem & 1023;
    const uint32_t nt = ol >> 6;
    const uint32_t lane = (ol >> 1) & 31;
    const uint32_t r = ol & 1;
    const uint32_t gc = lane >> 2;
    const uint32_t kk = (r << 3) | ((lane & 3) << 1);
    const uint32_t n = (nb << 7) + (nt << 3) + gc;
    const uint32_t k = (ks << 4) + kk;
    int j = 872 - (int)(qt << 7) + (int)n;
    j = j < 0 ? 0 : (j > 1998 ? 1998 : j);
    const float2 v = *(const float2*)(relE + (size_t)j * 64 + k);
    uint32_t hi, lo;
    split2(v.x, v.y, hi, lo);
    g_Eh[o] = hi;
    g_El[o] = lo;
}

// ===========================================================================
// fragment-direct projection GEMM (validated R8)
// dstsel: 0 -> Q planes, 1 -> K planes, 2 -> g_V fp32, 3 -> extDst
// ===========================================================================
__global__ void __launch_bounds__(256, 2) gemm_frag_kernel(
    const float* __restrict__ bias, float* extDst, int dstsel)
{
    const int tid = threadIdx.x;
    const int wid = tid >> 5;
    const int lane = tid & 31;
    const int wm = wid >> 2;
    const int wn = wid & 3;
    const int g = lane >> 2;
    const int tig = lane & 3;
    const int nb = blockIdx.x;
    const int rb = blockIdx.y;

    float acc[4][4][4];
#pragma unroll
    for (int i = 0; i < 4; i++)
#pragma unroll
        for (int j = 0; j < 4; j++)
#pragma unroll
            for (int r = 0; r < 4; r++) acc[i][j][r] = 0.f;

#pragma unroll 1
    for (int ks = 0; ks < 64; ks++) {
        const size_t abase = (size_t)((((rb << 6) + ks) << 3) + (wm << 2)) * 128 +
                             (lane << 2);
        const size_t bbase = (size_t)((((nb << 6) + ks) << 4) + (wn << 2)) * 64 +
                             (lane << 1);
        uint4 ah[4], al[4];
        uint2 bh[4], bl[4];
#pragma unroll
        for (int i = 0; i < 4; i++) {
            ah[i] = *(const uint4*)(g_Ah + abase + (i << 7));
            al[i] = *(const uint4*)(g_Al + abase + (i << 7));
        }
#pragma unroll
        for (int j = 0; j < 4; j++) {
            bh[j] = *(const uint2*)(g_Wh + bbase + (j << 6));
            bl[j] = *(const uint2*)(g_Wl + bbase + (j << 6));
        }
#pragma unroll
        for (int i = 0; i < 4; i++)
#pragma unroll
            for (int j = 0; j < 4; j++) {
                mma16816(acc[i][j], (const uint32_t*)&ah[i], (const uint32_t*)&bh[j]);
                mma16816(acc[i][j], (const uint32_t*)&ah[i], (const uint32_t*)&bl[j]);
                mma16816(acc[i][j], (const uint32_t*)&al[i], (const uint32_t*)&bh[j]);
            }
    }

    const int bm = rb << 7;
    const int bn = nb << 7;
#pragma unroll
    for (int i = 0; i < 4; i++) {
        const int m0 = bm + (wm << 6) + (i << 4) + g;
#pragma unroll
        for (int j = 0; j < 4; j++) {
            const int n = bn + (wn << 5) + (j << 3) + (tig << 1);
            const float2 bv = *(const float2*)(bias + n);
#pragma unroll
            for (int half = 0; half < 2; half++) {
                const int m = m0 + (half << 3);
                float2 o;
                o.x = acc[i][j][half * 2 + 0] + bv.x;
                o.y = acc[i][j][half * 2 + 1] + bv.y;
                if (dstsel <= 1) {
                    const int bh2 = ((m >> 10) << 4) + (n >> 6);
                    const int tile = (m >> 7) & 7;
                    const int row = m & 127;
                    const int d = n & 63;
                    uint32_t hi, lo;
                    split2(o.x, o.y, hi, lo);
                    const size_t base = ((size_t)((bh2 << 3) + tile)) << 12;
                    if (dstsel == 0) {
                        const size_t s = base + a_slot(row, d);
                        g_Qfh[s] = hi; g_Qfl[s] = lo;
                    } else {
                        const size_t s = base + b_slotN(row, d, 16);
                        g_Kfh[s] = hi; g_Kfl[s] = lo;
                    }
                } else if (dstsel == 2) {
                    const size_t idx = (((size_t)((m >> 10) * 16 + (n >> 6)) * 1024 +
                                        (size_t)(m & 1023)) << 6) + (n & 63);
                    *(float2*)(g_V + idx) = o;
                } else {
                    *(float2*)(extDst + (size_t)m * 1024 + n) = o;
                }
            }
        }
    }
}

// ===========================================================================
// G band GEMM (validated R7/R8, unchanged)
// ===========================================================================
__global__ void __launch_bounds__(256, 2) g_gemm_kernel()
{
    const int tid = threadIdx.x;
    const int wid = tid >> 5;
    const int lane = tid & 31;
    const int wm = wid >> 2;
    const int wn = wid & 3;
    const int g = lane >> 2;
    const int tig = lane & 3;
    const int nb = blockIdx.x;
    const int qt = blockIdx.y;
    const int bh = blockIdx.z;

    float acc[4][4][4];
#pragma unroll
    for (int i = 0; i < 4; i++)
#pragma unroll
        for (int j = 0; j < 4; j++)
#pragma unroll
            for (int r = 0; r < 4; r++) acc[i][j][r] = 0.f;

#pragma unroll
    for (int ks = 0; ks < 4; ks++) {
        const size_t abase = (size_t)(((((bh << 3) + qt) << 2) + ks) * 8 +
                                      (wm << 2)) * 128 + (lane << 2);
        const size_t bbase = (size_t)((((qt * 9 + nb) << 2) + ks) * 16 +
                                      (wn << 2)) * 64 + (lane << 1);
        uint4 ah[4], al[4];
        uint2 bh2[4], bl2[4];
#pragma unroll
        for (int i = 0; i < 4; i++) {
            ah[i] = *(const uint4*)(g_RQh + abase + (i << 7));
            al[i] = *(const uint4*)(g_RQl + abase + (i << 7));
        }
#pragma unroll
        for (int j = 0; j < 4; j++) {
            bh2[j] = *(const uint2*)(g_Eh + bbase + (j << 6));
            bl2[j] = *(const uint2*)(g_El + bbase + (j << 6));
        }
#pragma unroll
        for (int i = 0; i < 4; i++)
#pragma unroll
            for (int j = 0; j < 4; j++) {
                mma16816(acc[i][j], (const uint32_t*)&ah[i], (const uint32_t*)&bh2[j]);
                mma16816(acc[i][j], (const uint32_t*)&ah[i], (const uint32_t*)&bl2[j]);
                mma16816(acc[i][j], (const uint32_t*)&al[i], (const uint32_t*)&bh2[j]);
            }
    }

    float* Gb = g_G + (size_t)(((bh << 3) + qt) << 7) * 1152;
#pragma unroll
    for (int i = 0; i < 4; i++) {
        const int m0 = (wm << 6) + (i << 4) + g;
#pragma unroll
        for (int j = 0; j < 4; j++) {
            const int n = (nb << 7) + (wn << 5) + (j << 3) + (tig << 1);
#pragma unroll
            for (int half = 0; half < 2; half++) {
                const int m = m0 + (half << 3);
                *(float2*)(Gb + (size_t)m * 1152 + n) =
                    make_float2(acc[i][j][half * 2 + 0], acc[i][j][half * 2 + 1]);
            }
        }
    }
}

// ===========================================================================
// mask dtype-width detector (validated)
// ===========================================================================
__global__ void mask_detect_kernel(const unsigned int* __restrict__ m) {
    unsigned f = 0;
    for (unsigned i = blockIdx.x * blockDim.x + threadIdx.x; i < (1u << 20);
         i += blockDim.x * gridDim.x) {
        unsigned w = m[i];
        if (w == 0u) continue;
        unsigned lo = w & 0xFFFFu;
        if (lo == 0x3F80u || lo == 0x3C00u) f |= 1u;
        if (((w & 0xFEFEFEFEu) == 0u) && w > 1u) f |= 2u;
    }
    if (f) atomicOr(&g_mask_flags, (int)f);
}

// ===========================================================================
// qk_frag: S raw = Q.K^T, fragments streamed from planes (no staging)
// grid (kt, qt, bh); 8 warps; warp owns 16 q rows x 128 k.
// ===========================================================================
#define QK_SMEM_BYTES 67584

__global__ void __launch_bounds__(256, 1) qk_frag_kernel()
{
    extern __shared__ __align__(16) uint32_t sm[];
    const int tid = threadIdx.x;
    const int wid = tid >> 5;
    const int lane = tid & 31;
    const int g = lane >> 2;
    const int tig = lane & 3;
    const int kt = blockIdx.x, qt = blockIdx.y, bh = blockIdx.z;

    uint4 qh[4], ql[4];
    const size_t qbase = ((size_t)((bh << 3) + qt)) << 12;
#pragma unroll
    for (int s = 0; s < 4; s++) {
        const size_t ai = qbase + (((s << 3) + wid) << 7) + (lane << 2);
        qh[s] = *(const uint4*)(g_Qfh + ai);
        ql[s] = *(const uint4*)(g_Qfl + ai);
    }

    float acc[16][4];
#pragma unroll
    for (int j = 0; j < 16; j++)
#pragma unroll
        for (int r = 0; r < 4; r++) acc[j][r] = 0.f;

    const size_t kbase = ((size_t)((bh << 3) + kt)) << 12;
#pragma unroll
    for (int j = 0; j < 16; j++) {
#pragma unroll
        for (int s = 0; s < 4; s++) {
            const size_t bi = kbase + (((s << 4) + j) << 6) + (lane << 1);
            uint2 kh2 = *(const uint2*)(g_Kfh + bi);
            uint2 kl2 = *(const uint2*)(g_Kfl + bi);
            mma16816(acc[j], (const uint32_t*)&qh[s], (const uint32_t*)&kh2);
            mma16816(acc[j], (const uint32_t*)&qh[s], (const uint32_t*)&kl2);
            mma16816(acc[j], (const uint32_t*)&ql[s], (const uint32_t*)&kh2);
        }
    }

    // coalesced S write via padded smem restage (validated R5)
    float* stg = (float*)sm;
    {
        const int r0 = (wid << 4) + g;
#pragma unroll
        for (int j = 0; j < 16; j++) {
            const int col = (j << 3) + (tig << 1);
            *(float2*)&stg[r0 * 132 + col] = make_float2(acc[j][0], acc[j][1]);
            *(float2*)&stg[(r0 + 8) * 132 + col] = make_float2(acc[j][2], acc[j][3]);
        }
    }
    __syncthreads();

    float* Sb = g_S + ((size_t)bh << 20) + ((size_t)(qt << 7)) * 1024 + (kt << 7);
#pragma unroll
    for (int i = 0; i < 16; i++) {
        const int fi = tid + (i << 8);
        const int row = fi >> 5;
        const int c4 = (fi & 31) << 2;
        *(float4*)(Sb + (size_t)row * 1024 + c4) = *(const float4*)&stg[row * 132 + c4];
    }
}

// ===========================================================================
// fused softmax: v = (S + G) * 8, mask, softmax -> write P fragment planes
// ===========================================================================
__global__ void __launch_bounds__(256) softmax_kernel(const void* __restrict__ mask)
{
    const int row = blockIdx.x;
    const int q = row & 1023;
    const int bh = row >> 10;
    const int b = bh >> 4;
    float* Srow = g_S + (size_t)row * 1024;
    const size_t mb = ((size_t)(b << 10) + q) * 1024;
    const int tx = threadIdx.x;
    const int k = tx << 2;

    const int fl = g_mask_flags;
    const int wdt = (fl & 1) ? 2 : ((fl & 2) ? 1 : 4);

    const int qi = q & 127;
    const int qt = q >> 7;
    const float* Gp = g_G + ((size_t)(((bh << 3) + qt) << 7) + qi) * 1152 +
                      (127 - qi) + k;

    float4 sv = *(const float4*)(Srow + k);
    float v[4];
    v[0] = (sv.x + Gp[0]) * 8.0f;
    v[1] = (sv.y + Gp[1]) * 8.0f;
    v[2] = (sv.z + Gp[2]) * 8.0f;
    v[3] = (sv.w + Gp[3]) * 8.0f;
    const float NEG = __int_as_float(0xff800000);

    if (wdt == 4) {
        const unsigned int* mp = (const unsigned int*)mask + mb + k;
#pragma unroll
        for (int i = 0; i < 4; i++) if (mp[i]) v[i] = NEG;
    } else if (wdt == 2) {
        const unsigned short* mp = (const unsigned short*)mask + mb + k;
#pragma unroll
        for (int i = 0; i < 4; i++) if (mp[i]) v[i] = NEG;
    } else {
        const unsigned char* mp = (const unsigned char*)mask + mb + k;
#pragma unroll
        for (int i = 0; i < 4; i++) if (mp[i]) v[i] = NEG;
    }

    float mx = fmaxf(fmaxf(v[0], v[1]), fmaxf(v[2], v[3]));
#pragma unroll
    for (int off = 16; off; off >>= 1)
        mx = fmaxf(mx, __shfl_xor_sync(0xffffffffu, mx, off));
    __shared__ float red[8];
    if ((tx & 31) == 0) red[tx >> 5] = mx;
    __syncthreads();
    float rmax = red[0];
#pragma unroll
    for (int i = 1; i < 8; i++) rmax = fmaxf(rmax, red[i]);

    float e[4], s = 0.f;
#pragma unroll
    for (int i = 0; i < 4; i++) { e[i] = expf(v[i] - rmax); s += e[i]; }
#pragma unroll
    for (int off = 16; off; off >>= 1)
        s += __shfl_xor_sync(0xffffffffu, s, off);
    __syncthreads();
    if ((tx & 31) == 0) red[tx >> 5] = s;
    __syncthreads();
    float rs = 0.f;
#pragma unroll
    for (int i = 0; i < 8; i++) rs += red[i];
    const float inv = 1.0f / rs;

    // write P as fragment planes: tile (bh, qt, kc = k>>7), slot via a_slot
    const size_t pbase = ((size_t)((((bh << 3) + qt) << 3) + (k >> 7))) << 13;
    const int kl = k & 127;
    uint32_t hi0, lo0, hi1, lo1;
    split2(e[0] * inv, e[1] * inv, hi0, lo0);
    split2(e[2] * inv, e[3] * inv, hi1, lo1);
    const size_t s0 = pbase + a_slot(qi, kl);
    const size_t s1 = pbase + a_slot(qi, kl + 2);
    g_Pfh[s0] = hi0; g_Pfl[s0] = lo0;
    g_Pfh[s1] = hi1; g_Pfl[s1] = lo1;
}

// ===========================================================================
// av_frag: O = P.V, both operands streamed from fragment planes. No SMEM.
// grid (qt 8, bh 64); 8 warps; warp owns 16 q rows x 64 d.
// ===========================================================================
__global__ void __launch_bounds__(256) av_frag_kernel()
{
    const int tid = threadIdx.x;
    const int wid = tid >> 5;
    const int lane = tid & 31;
    const int g = lane >> 2;
    const int tig = lane & 3;
    const int qt = blockIdx.x;
    const int bh = blockIdx.y;
    const int b = bh >> 4, h = bh & 15;

    float o[8][4];
#pragma unroll
    for (int j = 0; j < 8; j++)
#pragma unroll
        for (int r = 0; r < 4; r++) o[j][r] = 0.f;

#pragma unroll 1
    for (int kc = 0; kc < 8; kc++) {
        const size_t pbase = ((size_t)((((bh << 3) + qt) << 3) + kc)) << 13;
        const size_t vbase = ((size_t)((bh << 3) + kc)) << 12;
#pragma unroll
        for (int s = 0; s < 8; s++) {
            const size_t ai = pbase + (((s << 3) + wid) << 7) + (lane << 2);
            uint4 ph = *(const uint4*)(g_Pfh + ai);
            uint4 pl = *(const uint4*)(g_Pfl + ai);
#pragma unroll
            for (int j = 0; j < 8; j++) {
                const size_t bi = vbase + (((s << 3) + j) << 6) + (lane << 1);
                uint2 vh = *(const uint2*)(g_Vfh + bi);
                uint2 vl = *(const uint2*)(g_Vfl + bi);
                mma16816(o[j], (const uint32_t*)&ph, (const uint32_t*)&vh);
                mma16816(o[j], (const uint32_t*)&ph, (const uint32_t*)&vl);
                mma16816(o[j], (const uint32_t*)&pl, (const uint32_t*)&vh);
            }
        }
    }

    const int qrow = (qt << 7) + (wid << 4) + g;
#pragma unroll
    for (int j = 0; j < 8; j++) {
        const int d = (j << 3) + (tig << 1);
        float* op = g_O + ((size_t)(b * 1024 + qrow)) * 1024 + h * 64 + d;
        *(float2*)op = make_float2(o[j][0], o[j][1]);
        *(float2*)(op + (size_t)8 * 1024) = make_float2(o[j][2], o[j][3]);
    }
}

// ===========================================================================
// Launch
// ===========================================================================
extern "C" void kernel_launch(void* const* d_in, const int* in_sizes, int n_in,
                              void* d_out, int out_size)
{
    const float* query = (const float*)d_in[0];
    const float* key_i = (const float*)d_in[1];
    const float* value = (const float*)d_in[2];
    const void*  mask  = d_in[3];
    const float* q_w = (const float*)d_in[4];
    const float* q_b = (const float*)d_in[5];
    const float* k_w = (const float*)d_in[6];
    const float* k_b = (const float*)d_in[7];
    const float* v_w = (const float*)d_in[8];
    const float* v_b = (const float*)d_in[9];
    const float* o_w = (const float*)d_in[10];
    const float* o_b = (const float*)d_in[11];
    const float* relE = (const float*)d_in[12];
    float* out = (float*)d_out;

    static int attr_set = 0;
    if (!attr_set) {
        cudaFuncSetAttribute(qk_frag_kernel,
                             cudaFuncAttributeMaxDynamicSharedMemorySize,
                             QK_SMEM_BYTES);
        attr_set = 1;
    }

    dim3 gf(8, 32);

    conv_a_kernel<<<8192, 256>>>(query, 0);
    conv_b_kernel<<<2048, 256>>>(q_w);
    gemm_frag_kernel<<<gf, 256>>>(q_b, nullptr, 0);

    conv_a_kernel<<<8192, 256>>>(key_i, 0);
    conv_b_kernel<<<2048, 256>>>(k_w);
    gemm_frag_kernel<<<gf, 256>>>(k_b, nullptr, 1);

    conv_a_kernel<<<8192, 256>>>(value, 0);
    conv_b_kernel<<<2048, 256>>>(v_w);
    gemm_frag_kernel<<<gf, 256>>>(v_b, nullptr, 2);
    conv_v_kernel<<<8192, 256>>>();

    conv_rq_kernel<<<8192, 256>>>(query);
    conv_e_kernel<<<1152, 256>>>(relE);
    g_gemm_kernel<<<dim3(9, 8, 64), 256>>>();

    mask_detect_kernel<<<256, 256>>>((const unsigned int*)mask);

    qk_frag_kernel<<<dim3(8, 8, 64), 256, QK_SMEM_BYTES>>>();
    softmax_kernel<<<65536, 256>>>(mask);
    av_frag_kernel<<<dim3(8, 64), 256>>>();

    conv_a_kernel<<<8192, 256>>>(nullptr, 1);
    conv_b_kernel<<<2048, 256>>>(o_w);
    gemm_frag_kernel<<<gf, 256>>>(o_b, out, 3);
}

// round 11
// speedup vs baseline: 1.5838x; 1.0034x over previous
#include <cuda_runtime.h>
#include <cuda_bf16.h>
#include <cstdint>
#include <cstddef>

#define BB 4
#define TT 1024
#define HH 16
#define DD 64
#define CC 1024
#define MM 4096

__device__ float g_V[(size_t)BB * HH * TT * DD];
__device__ float g_S[(size_t)BB * HH * TT * TT];
__device__ float g_O[(size_t)MM * CC];
__device__ int   g_mask_flags;

// fragment-ordered bf16 planes (u32 = packed bf16x2)
__device__ uint32_t g_Ah[(size_t)MM * CC / 2];
__device__ uint32_t g_Al[(size_t)MM * CC / 2];
__device__ uint32_t g_Wh[(size_t)CC * CC / 2];
__device__ uint32_t g_Wl[(size_t)CC * CC / 2];

// Q/K/V attention fragment planes: 64 bh x 8 tiles x 4096 u32
__device__ uint32_t g_Qfh[(size_t)64 * 8 * 4096];
__device__ uint32_t g_Qfl[(size_t)64 * 8 * 4096];
__device__ uint32_t g_Kfh[(size_t)64 * 8 * 4096];
__device__ uint32_t g_Kfl[(size_t)64 * 8 * 4096];
__device__ uint32_t g_Vfh[(size_t)64 * 8 * 4096];
__device__ uint32_t g_Vfl[(size_t)64 * 8 * 4096];

// P fragment planes: 64 bh x 8 qt x 8 kc x 8192 u32
__device__ uint32_t g_Pfh[(size_t)4096 * 8192];
__device__ uint32_t g_Pfl[(size_t)4096 * 8192];

// rpe band-GEMM operands + result
__device__ uint32_t g_RQh[(size_t)64 * 8 * 4096];
__device__ uint32_t g_RQl[(size_t)64 * 8 * 4096];
__device__ uint32_t g_Eh[(size_t)8 * 9 * 4 * 1024];
__device__ uint32_t g_El[(size_t)8 * 9 * 4 * 1024];
__device__ float    g_G[(size_t)64 * 8 * 128 * 1152];

// ===========================================================================
// shared helpers (validated R4-R8)
// ===========================================================================
__device__ __forceinline__ void mma16816(float* c, const uint32_t* a,
                                         const uint32_t* b) {
    asm volatile(
        "mma.sync.aligned.m16n8k16.row.col.f32.bf16.bf16.f32 "
        "{%0,%1,%2,%3}, {%4,%5,%6,%7}, {%8,%9}, {%0,%1,%2,%3};"
        : "+f"(c[0]), "+f"(c[1]), "+f"(c[2]), "+f"(c[3])
        : "r"(a[0]), "r"(a[1]), "r"(a[2]), "r"(a[3]), "r"(b[0]), "r"(b[1]));
}

__device__ __forceinline__ void split2(float x, float y, uint32_t& hi, uint32_t& lo) {
    __nv_bfloat16 hx = __float2bfloat16(x);
    __nv_bfloat16 hy = __float2bfloat16(y);
    __nv_bfloat16 lx = __float2bfloat16(x - __bfloat162float(hx));
    __nv_bfloat16 ly = __float2bfloat16(y - __bfloat162float(hy));
    hi = ((uint32_t)__bfloat16_as_ushort(hy) << 16) | __bfloat16_as_ushort(hx);
    lo = ((uint32_t)__bfloat16_as_ushort(ly) << 16) | __bfloat16_as_ushort(lx);
}

__device__ __forceinline__ int a_slot(int row, int k) {
    const int kstep = k >> 4, kk = k & 15;
    const int mt = row >> 4, rit = row & 15;
    const int lane = ((rit & 7) << 2) | ((kk >> 1) & 3);
    const int r = (rit >> 3) | (((kk >> 3) & 1) << 1);
    return (((kstep << 3) + mt) << 7) + (lane << 2) + r;
}
__device__ __forceinline__ int b_slotN(int n, int k, int NT) {
    const int kstep = k >> 4, kk = k & 15;
    const int nt = n >> 3, gc = n & 7;
    const int lane = (gc << 2) | ((kk >> 1) & 3);
    const int r = (kk >> 3) & 1;
    return (((kstep * NT) + nt) << 6) + (lane << 1) + r;
}

// ===========================================================================
// converters (validated)
// ===========================================================================
__global__ void __launch_bounds__(256) conv_a_kernel(const float* __restrict__ ext,
                                                     int srcsel)
{
    const float* src = srcsel ? g_O : ext;
    const uint32_t o = blockIdx.x * 256 + threadIdx.x;
    const uint32_t region = o >> 10;
    const uint32_t rb = region >> 6, ks = region & 63;
    const uint32_t ol = o & 1023;
    const uint32_t mt = ol >> 7;
    const uint32_t lane = (ol >> 2) & 31;
    const uint32_t r = ol & 3;
    const uint32_t rit = ((r & 1) << 3) | (lane >> 2);
    const uint32_t kk = ((r >> 1) << 3) | ((lane & 3) << 1);
    const uint32_t row = (rb << 7) + (mt << 4) + rit;
    const uint32_t k = (ks << 4) + kk;
    const float2 v = *(const float2*)(src + (size_t)row * 1024 + k);
    uint32_t hi, lo;
    split2(v.x, v.y, hi, lo);
    g_Ah[o] = hi;
    g_Al[o] = lo;
}

__global__ void __launch_bounds__(256) conv_b_kernel(const float* __restrict__ w)
{
    const uint32_t o = blockIdx.x * 256 + threadIdx.x;
    const uint32_t region = o >> 10;
    const uint32_t nb = region >> 6, ks = region & 63;
    const uint32_t ol = o & 1023;
    const uint32_t nt = ol >> 6;
    const uint32_t lane = (ol >> 1) & 31;
    const uint32_t r = ol & 1;
    const uint32_t gc = lane >> 2;
    const uint32_t kk = (r << 3) | ((lane & 3) << 1);
    const uint32_t n = (nb << 7) + (nt << 3) + gc;
    const uint32_t k = (ks << 4) + kk;
    const float2 v = *(const float2*)(w + (size_t)n * 1024 + k);
    uint32_t hi, lo;
    split2(v.x, v.y, hi, lo);
    g_Wh[o] = hi;
    g_Wl[o] = lo;
}

// g_V fp32 head layout -> V fragment planes (validated R8)
__global__ void __launch_bounds__(256) conv_v_kernel()
{
    const uint32_t o = blockIdx.x * 256 + threadIdx.x;
    const uint32_t region = o >> 12;
    const uint32_t bh = region >> 3, kt = region & 7;
    const uint32_t ol = o & 4095;
    const uint32_t ks = ol >> 9;
    const uint32_t nt = (ol >> 6) & 7;
    const uint32_t lane = (ol >> 1) & 31;
    const uint32_t r = ol & 1;
    const uint32_t d = (nt << 3) + (lane >> 2);
    const uint32_t key = (ks << 4) + ((r << 3) | ((lane & 3) << 1));
    const size_t vb = ((size_t)bh * 1024 + (kt << 7) + key) * 64 + d;
    const float v0 = g_V[vb];
    const float v1 = g_V[vb + 64];
    uint32_t hi, lo;
    split2(v0, v1, hi, lo);
    g_Vfh[o] = hi;
    g_Vfl[o] = lo;
}

__global__ void __launch_bounds__(256) conv_rq_kernel(const float* __restrict__ q)
{
    const uint32_t o = blockIdx.x * 256 + threadIdx.x;
    const uint32_t region = o >> 10;
    const uint32_t bhqt = region >> 2, ks = region & 3;
    const uint32_t bh = bhqt >> 3, qt = bhqt & 7;
    const uint32_t b = bh >> 4, h = bh & 15;
    const uint32_t ol = o & 1023;
    const uint32_t mt = ol >> 7;
    const uint32_t lane = (ol >> 2) & 31;
    const uint32_t r = ol & 3;
    const uint32_t rit = ((r & 1) << 3) | (lane >> 2);
    const uint32_t kk = ((r >> 1) << 3) | ((lane & 3) << 1);
    const uint32_t row = (qt << 7) + (mt << 4) + rit;
    const uint32_t k = (ks << 4) + kk;
    const float2 v = *(const float2*)(q + ((size_t)(b * 1024 + row)) * 1024 +
                                      h * 64 + k);
    uint32_t hi, lo;
    split2(v.x, v.y, hi, lo);
    g_RQh[o] = hi;
    g_RQl[o] = lo;
}

__global__ void __launch_bounds__(256) conv_e_kernel(const float* __restrict__ relE)
{
    const uint32_t o = blockIdx.x * 256 + threadIdx.x;
    const uint32_t qt = o / 36864;
    const uint32_t rem = o - qt * 36864;
    const uint32_t region = rem >> 10;
    const uint32_t nb = region >> 2, ks = region & 3;
    const uint32_t ol = rem & 1023;
    const uint32_t nt = ol >> 6;
    const uint32_t lane = (ol >> 1) & 31;
    const uint32_t r = ol & 1;
    const uint32_t gc = lane >> 2;
    const uint32_t kk = (r << 3) | ((lane & 3) << 1);
    const uint32_t n = (nb << 7) + (nt << 3) + gc;
    const uint32_t k = (ks << 4) + kk;
    int j = 872 - (int)(qt << 7) + (int)n;
    j = j < 0 ? 0 : (j > 1998 ? 1998 : j);
    const float2 v = *(const float2*)(relE + (size_t)j * 64 + k);
    uint32_t hi, lo;
    split2(v.x, v.y, hi, lo);
    g_Eh[o] = hi;
    g_El[o] = lo;
}

// ===========================================================================
// fragment-direct projection GEMM (validated R8)
// dstsel: 0 -> Q planes, 1 -> K planes, 2 -> g_V fp32, 3 -> extDst
// ===========================================================================
__global__ void __launch_bounds__(256, 2) gemm_frag_kernel(
    const float* __restrict__ bias, float* extDst, int dstsel)
{
    const int tid = threadIdx.x;
    const int wid = tid >> 5;
    const int lane = tid & 31;
    const int wm = wid >> 2;
    const int wn = wid & 3;
    const int g = lane >> 2;
    const int tig = lane & 3;
    const int nb = blockIdx.x;
    const int rb = blockIdx.y;

    float acc[4][4][4];
#pragma unroll
    for (int i = 0; i < 4; i++)
#pragma unroll
        for (int j = 0; j < 4; j++)
#pragma unroll
            for (int r = 0; r < 4; r++) acc[i][j][r] = 0.f;

#pragma unroll 1
    for (int ks = 0; ks < 64; ks++) {
        const size_t abase = (size_t)((((rb << 6) + ks) << 3) + (wm << 2)) * 128 +
                             (lane << 2);
        const size_t bbase = (size_t)((((nb << 6) + ks) << 4) + (wn << 2)) * 64 +
                             (lane << 1);
        uint4 ah[4], al[4];
        uint2 bh[4], bl[4];
#pragma unroll
        for (int i = 0; i < 4; i++) {
            ah[i] = *(const uint4*)(g_Ah + abase + (i << 7));
            al[i] = *(const uint4*)(g_Al + abase + (i << 7));
        }
#pragma unroll
        for (int j = 0; j < 4; j++) {
            bh[j] = *(const uint2*)(g_Wh + bbase + (j << 6));
            bl[j] = *(const uint2*)(g_Wl + bbase + (j << 6));
        }
#pragma unroll
        for (int i = 0; i < 4; i++)
#pragma unroll
            for (int j = 0; j < 4; j++) {
                mma16816(acc[i][j], (const uint32_t*)&ah[i], (const uint32_t*)&bh[j]);
                mma16816(acc[i][j], (const uint32_t*)&ah[i], (const uint32_t*)&bl[j]);
                mma16816(acc[i][j], (const uint32_t*)&al[i], (const uint32_t*)&bh[j]);
            }
    }

    const int bm = rb << 7;
    const int bn = nb << 7;
#pragma unroll
    for (int i = 0; i < 4; i++) {
        const int m0 = bm + (wm << 6) + (i << 4) + g;
#pragma unroll
        for (int j = 0; j < 4; j++) {
            const int n = bn + (wn << 5) + (j << 3) + (tig << 1);
            const float2 bv = *(const float2*)(bias + n);
#pragma unroll
            for (int half = 0; half < 2; half++) {
                const int m = m0 + (half << 3);
                float2 o;
                o.x = acc[i][j][half * 2 + 0] + bv.x;
                o.y = acc[i][j][half * 2 + 1] + bv.y;
                if (dstsel <= 1) {
                    const int bh2 = ((m >> 10) << 4) + (n >> 6);
                    const int tile = (m >> 7) & 7;
                    const int row = m & 127;
                    const int d = n & 63;
                    uint32_t hi, lo;
                    split2(o.x, o.y, hi, lo);
                    const size_t base = ((size_t)((bh2 << 3) + tile)) << 12;
                    if (dstsel == 0) {
                        const size_t s = base + a_slot(row, d);
                        g_Qfh[s] = hi; g_Qfl[s] = lo;
                    } else {
                        const size_t s = base + b_slotN(row, d, 16);
                        g_Kfh[s] = hi; g_Kfl[s] = lo;
                    }
                } else if (dstsel == 2) {
                    const size_t idx = (((size_t)((m >> 10) * 16 + (n >> 6)) * 1024 +
                                        (size_t)(m & 1023)) << 6) + (n & 63);
                    *(float2*)(g_V + idx) = o;
                } else {
                    *(float2*)(extDst + (size_t)m * 1024 + n) = o;
                }
            }
        }
    }
}

// ===========================================================================
// G band GEMM (validated R7/R8, unchanged)
// ===========================================================================
__global__ void __launch_bounds__(256, 2) g_gemm_kernel()
{
    const int tid = threadIdx.x;
    const int wid = tid >> 5;
    const int lane = tid & 31;
    const int wm = wid >> 2;
    const int wn = wid & 3;
    const int g = lane >> 2;
    const int tig = lane & 3;
    const int nb = blockIdx.x;
    const int qt = blockIdx.y;
    const int bh = blockIdx.z;

    float acc[4][4][4];
#pragma unroll
    for (int i = 0; i < 4; i++)
#pragma unroll
        for (int j = 0; j < 4; j++)
#pragma unroll
            for (int r = 0; r < 4; r++) acc[i][j][r] = 0.f;

#pragma unroll
    for (int ks = 0; ks < 4; ks++) {
        const size_t abase = (size_t)(((((bh << 3) + qt) << 2) + ks) * 8 +
                                      (wm << 2)) * 128 + (lane << 2);
        const size_t bbase = (size_t)((((qt * 9 + nb) << 2) + ks) * 16 +
                                      (wn << 2)) * 64 + (lane << 1);
        uint4 ah[4], al[4];
        uint2 bh2[4], bl2[4];
#pragma unroll
        for (int i = 0; i < 4; i++) {
            ah[i] = *(const uint4*)(g_RQh + abase + (i << 7));
            al[i] = *(const uint4*)(g_RQl + abase + (i << 7));
        }
#pragma unroll
        for (int j = 0; j < 4; j++) {
            bh2[j] = *(const uint2*)(g_Eh + bbase + (j << 6));
            bl2[j] = *(const uint2*)(g_El + bbase + (j << 6));
        }
#pragma unroll
        for (int i = 0; i < 4; i++)
#pragma unroll
            for (int j = 0; j < 4; j++) {
                mma16816(acc[i][j], (const uint32_t*)&ah[i], (const uint32_t*)&bh2[j]);
                mma16816(acc[i][j], (const uint32_t*)&ah[i], (const uint32_t*)&bl2[j]);
                mma16816(acc[i][j], (const uint32_t*)&al[i], (const uint32_t*)&bh2[j]);
            }
    }

    float* Gb = g_G + (size_t)(((bh << 3) + qt) << 7) * 1152;
#pragma unroll
    for (int i = 0; i < 4; i++) {
        const int m0 = (wm << 6) + (i << 4) + g;
#pragma unroll
        for (int j = 0; j < 4; j++) {
            const int n = (nb << 7) + (wn << 5) + (j << 3) + (tig << 1);
#pragma unroll
            for (int half = 0; half < 2; half++) {
                const int m = m0 + (half << 3);
                *(float2*)(Gb + (size_t)m * 1152 + n) =
                    make_float2(acc[i][j][half * 2 + 0], acc[i][j][half * 2 + 1]);
            }
        }
    }
}

// ===========================================================================
// mask dtype-width detector (validated)
// ===========================================================================
__global__ void mask_detect_kernel(const unsigned int* __restrict__ m) {
    unsigned f = 0;
    for (unsigned i = blockIdx.x * blockDim.x + threadIdx.x; i < (1u << 20);
         i += blockDim.x * gridDim.x) {
        unsigned w = m[i];
        if (w == 0u) continue;
        unsigned lo = w & 0xFFFFu;
        if (lo == 0x3F80u || lo == 0x3C00u) f |= 1u;
        if (((w & 0xFEFEFEFEu) == 0u) && w > 1u) f |= 2u;
    }
    if (f) atomicOr(&g_mask_flags, (int)f);
}

// ===========================================================================
// qk_frag: S raw = Q.K^T, fragments streamed from planes (no staging)
// grid (kt, qt, bh); 8 warps; warp owns 16 q rows x 128 k.
// ===========================================================================
#define QK_SMEM_BYTES 67584

__global__ void __launch_bounds__(256, 1) qk_frag_kernel()
{
    extern __shared__ __align__(16) uint32_t sm[];
    const int tid = threadIdx.x;
    const int wid = tid >> 5;
    const int lane = tid & 31;
    const int g = lane >> 2;
    const int tig = lane & 3;
    const int kt = blockIdx.x, qt = blockIdx.y, bh = blockIdx.z;

    uint4 qh[4], ql[4];
    const size_t qbase = ((size_t)((bh << 3) + qt)) << 12;
#pragma unroll
    for (int s = 0; s < 4; s++) {
        const size_t ai = qbase + (((s << 3) + wid) << 7) + (lane << 2);
        qh[s] = *(const uint4*)(g_Qfh + ai);
        ql[s] = *(const uint4*)(g_Qfl + ai);
    }

    float acc[16][4];
#pragma unroll
    for (int j = 0; j < 16; j++)
#pragma unroll
        for (int r = 0; r < 4; r++) acc[j][r] = 0.f;

    const size_t kbase = ((size_t)((bh << 3) + kt)) << 12;
#pragma unroll
    for (int j = 0; j < 16; j++) {
#pragma unroll
        for (int s = 0; s < 4; s++) {
            const size_t bi = kbase + (((s << 4) + j) << 6) + (lane << 1);
            uint2 kh2 = *(const uint2*)(g_Kfh + bi);
            uint2 kl2 = *(const uint2*)(g_Kfl + bi);
            mma16816(acc[j], (const uint32_t*)&qh[s], (const uint32_t*)&kh2);
            mma16816(acc[j], (const uint32_t*)&qh[s], (const uint32_t*)&kl2);
            mma16816(acc[j], (const uint32_t*)&ql[s], (const uint32_t*)&kh2);
        }
    }

    // coalesced S write via padded smem restage (validated R5)
    float* stg = (float*)sm;
    {
        const int r0 = (wid << 4) + g;
#pragma unroll
        for (int j = 0; j < 16; j++) {
            const int col = (j << 3) + (tig << 1);
            *(float2*)&stg[r0 * 132 + col] = make_float2(acc[j][0], acc[j][1]);
            *(float2*)&stg[(r0 + 8) * 132 + col] = make_float2(acc[j][2], acc[j][3]);
        }
    }
    __syncthreads();

    float* Sb = g_S + ((size_t)bh << 20) + ((size_t)(qt << 7)) * 1024 + (kt << 7);
#pragma unroll
    for (int i = 0; i < 16; i++) {
        const int fi = tid + (i << 8);
        const int row = fi >> 5;
        const int c4 = (fi & 31) << 2;
        *(float4*)(Sb + (size_t)row * 1024 + c4) = *(const float4*)&stg[row * 132 + c4];
    }
}

// ===========================================================================
// fused softmax: v = (S + G) * 8, mask, softmax -> write P fragment planes
// ===========================================================================
__global__ void __launch_bounds__(256) softmax_kernel(const void* __restrict__ mask)
{
    const int row = blockIdx.x;
    const int q = row & 1023;
    const int bh = row >> 10;
    const int b = bh >> 4;
    float* Srow = g_S + (size_t)row * 1024;
    const size_t mb = ((size_t)(b << 10) + q) * 1024;
    const int tx = threadIdx.x;
    const int k = tx << 2;

    const int fl = g_mask_flags;
    const int wdt = (fl & 1) ? 2 : ((fl & 2) ? 1 : 4);

    const int qi = q & 127;
    const int qt = q >> 7;
    const float* Gp = g_G + ((size_t)(((bh << 3) + qt) << 7) + qi) * 1152 +
                      (127 - qi) + k;

    float4 sv = *(const float4*)(Srow + k);
    float v[4];
    v[0] = (sv.x + Gp[0]) * 8.0f;
    v[1] = (sv.y + Gp[1]) * 8.0f;
    v[2] = (sv.z + Gp[2]) * 8.0f;
    v[3] = (sv.w + Gp[3]) * 8.0f;
    const float NEG = __int_as_float(0xff800000);

    if (wdt == 4) {
        const unsigned int* mp = (const unsigned int*)mask + mb + k;
#pragma unroll
        for (int i = 0; i < 4; i++) if (mp[i]) v[i] = NEG;
    } else if (wdt == 2) {
        const unsigned short* mp = (const unsigned short*)mask + mb + k;
#pragma unroll
        for (int i = 0; i < 4; i++) if (mp[i]) v[i] = NEG;
    } else {
        const unsigned char* mp = (const unsigned char*)mask + mb + k;
#pragma unroll
        for (int i = 0; i < 4; i++) if (mp[i]) v[i] = NEG;
    }

    float mx = fmaxf(fmaxf(v[0], v[1]), fmaxf(v[2], v[3]));
#pragma unroll
    for (int off = 16; off; off >>= 1)
        mx = fmaxf(mx, __shfl_xor_sync(0xffffffffu, mx, off));
    __shared__ float red[8];
    if ((tx & 31) == 0) red[tx >> 5] = mx;
    __syncthreads();
    float rmax = red[0];
#pragma unroll
    for (int i = 1; i < 8; i++) rmax = fmaxf(rmax, red[i]);

    float e[4], s = 0.f;
#pragma unroll
    for (int i = 0; i < 4; i++) { e[i] = expf(v[i] - rmax); s += e[i]; }
#pragma unroll
    for (int off = 16; off; off >>= 1)
        s += __shfl_xor_sync(0xffffffffu, s, off);
    __syncthreads();
    if ((tx & 31) == 0) red[tx >> 5] = s;
    __syncthreads();
    float rs = 0.f;
#pragma unroll
    for (int i = 0; i < 8; i++) rs += red[i];
    const float inv = 1.0f / rs;

    // write P as fragment planes: tile (bh, qt, kc = k>>7), slot via a_slot
    const size_t pbase = ((size_t)((((bh << 3) + qt) << 3) + (k >> 7))) << 13;
    const int kl = k & 127;
    uint32_t hi0, lo0, hi1, lo1;
    split2(e[0] * inv, e[1] * inv, hi0, lo0);
    split2(e[2] * inv, e[3] * inv, hi1, lo1);
    const size_t s0 = pbase + a_slot(qi, kl);
    const size_t s1 = pbase + a_slot(qi, kl + 2);
    g_Pfh[s0] = hi0; g_Pfl[s0] = lo0;
    g_Pfh[s1] = hi1; g_Pfl[s1] = lo1;
}

// ===========================================================================
// av_frag: O = P.V, both operands streamed from fragment planes. No SMEM.
// grid (qt 8, bh 64); 8 warps; warp owns 16 q rows x 64 d.
// ===========================================================================
__global__ void __launch_bounds__(256) av_frag_kernel()
{
    const int tid = threadIdx.x;
    const int wid = tid >> 5;
    const int lane = tid & 31;
    const int g = lane >> 2;
    const int tig = lane & 3;
    const int qt = blockIdx.x;
    const int bh = blockIdx.y;
    const int b = bh >> 4, h = bh & 15;

    float o[8][4];
#pragma unroll
    for (int j = 0; j < 8; j++)
#pragma unroll
        for (int r = 0; r < 4; r++) o[j][r] = 0.f;

#pragma unroll 1
    for (int kc = 0; kc < 8; kc++) {
        const size_t pbase = ((size_t)((((bh << 3) + qt) << 3) + kc)) << 13;
        const size_t vbase = ((size_t)((bh << 3) + kc)) << 12;
#pragma unroll
        for (int s = 0; s < 8; s++) {
            const size_t ai = pbase + (((s << 3) + wid) << 7) + (lane << 2);
            uint4 ph = *(const uint4*)(g_Pfh + ai);
            uint4 pl = *(const uint4*)(g_Pfl + ai);
#pragma unroll
            for (int j = 0; j < 8; j++) {
                const size_t bi = vbase + (((s << 3) + j) << 6) + (lane << 1);
                uint2 vh = *(const uint2*)(g_Vfh + bi);
                uint2 vl = *(const uint2*)(g_Vfl + bi);
                mma16816(o[j], (const uint32_t*)&ph, (const uint32_t*)&vh);
                mma16816(o[j], (const uint32_t*)&ph, (const uint32_t*)&vl);
                mma16816(o[j], (const uint32_t*)&pl, (const uint32_t*)&vh);
            }
        }
    }

    const int qrow = (qt << 7) + (wid << 4) + g;
#pragma unroll
    for (int j = 0; j < 8; j++) {
        const int d = (j << 3) + (tig << 1);
        float* op = g_O + ((size_t)(b * 1024 + qrow)) * 1024 + h * 64 + d;
        *(float2*)op = make_float2(o[j][0], o[j][1]);
        *(float2*)(op + (size_t)8 * 1024) = make_float2(o[j][2], o[j][3]);
    }
}

// ===========================================================================
// Launch
// ===========================================================================
extern "C" void kernel_launch(void* const* d_in, const int* in_sizes, int n_in,
                              void* d_out, int out_size)
{
    const float* query = (const float*)d_in[0];
    const float* key_i = (const float*)d_in[1];
    const float* value = (const float*)d_in[2];
    const void*  mask  = d_in[3];
    const float* q_w = (const float*)d_in[4];
    const float* q_b = (const float*)d_in[5];
    const float* k_w = (const float*)d_in[6];
    const float* k_b = (const float*)d_in[7];
    const float* v_w = (const float*)d_in[8];
    const float* v_b = (const float*)d_in[9];
    const float* o_w = (const float*)d_in[10];
    const float* o_b = (const float*)d_in[11];
    const float* relE = (const float*)d_in[12];
    float* out = (float*)d_out;

    static int attr_set = 0;
    if (!attr_set) {
        cudaFuncSetAttribute(qk_frag_kernel,
                             cudaFuncAttributeMaxDynamicSharedMemorySize,
                             QK_SMEM_BYTES);
        attr_set = 1;
    }

    dim3 gf(8, 32);

    conv_a_kernel<<<8192, 256>>>(query, 0);
    conv_b_kernel<<<2048, 256>>>(q_w);
    gemm_frag_kernel<<<gf, 256>>>(q_b, nullptr, 0);

    conv_a_kernel<<<8192, 256>>>(key_i, 0);
    conv_b_kernel<<<2048, 256>>>(k_w);
    gemm_frag_kernel<<<gf, 256>>>(k_b, nullptr, 1);

    conv_a_kernel<<<8192, 256>>>(value, 0);
    conv_b_kernel<<<2048, 256>>>(v_w);
    gemm_frag_kernel<<<gf, 256>>>(v_b, nullptr, 2);
    conv_v_kernel<<<8192, 256>>>();

    conv_rq_kernel<<<8192, 256>>>(query);
    conv_e_kernel<<<1152, 256>>>(relE);
    g_gemm_kernel<<<dim3(9, 8, 64), 256>>>();

    mask_detect_kernel<<<256, 256>>>((const unsigned int*)mask);

    qk_frag_kernel<<<dim3(8, 8, 64), 256, QK_SMEM_BYTES>>>();
    softmax_kernel<<<65536, 256>>>(mask);
    av_frag_kernel<<<dim3(8, 64), 256>>>();

    conv_a_kernel<<<8192, 256>>>(nullptr, 1);
    conv_b_kernel<<<2048, 256>>>(o_w);
    gemm_frag_kernel<<<gf, 256>>>(o_b, out, 3);
}

// round 13
// speedup vs baseline: 1.9838x; 1.2525x over previous
#include <cuda_runtime.h>
#include <cuda_bf16.h>
#include <cstdint>
#include <cstddef>

#define BB 4
#define TT 1024
#define HH 16
#define DD 64
#define CC 1024
#define MM 4096

__device__ float g_V[(size_t)BB * HH * TT * DD];
__device__ float g_S[(size_t)BB * HH * TT * TT];
__device__ float g_O[(size_t)MM * CC];
__device__ int   g_mask_flags;

__device__ uint32_t g_Ah[3][(size_t)MM * CC / 2];
__device__ uint32_t g_Al[3][(size_t)MM * CC / 2];
__device__ uint32_t g_Wh[3][(size_t)CC * CC / 2];
__device__ uint32_t g_Wl[3][(size_t)CC * CC / 2];

__device__ uint32_t g_Qfh[(size_t)64 * 8 * 4096];
__device__ uint32_t g_Qfl[(size_t)64 * 8 * 4096];
__device__ uint32_t g_Kfh[(size_t)64 * 8 * 4096];
__device__ uint32_t g_Kfl[(size_t)64 * 8 * 4096];
__device__ uint32_t g_Vfh[(size_t)64 * 8 * 4096];
__device__ uint32_t g_Vfl[(size_t)64 * 8 * 4096];

__device__ uint32_t g_Pfh[(size_t)4096 * 8192];
__device__ uint32_t g_Pfl[(size_t)4096 * 8192];

__device__ uint32_t g_RQh[(size_t)64 * 8 * 4096];
__device__ uint32_t g_RQl[(size_t)64 * 8 * 4096];
__device__ uint32_t g_Eh[(size_t)8 * 9 * 4 * 1024];
__device__ uint32_t g_El[(size_t)8 * 9 * 4 * 1024];
__device__ float    g_G[(size_t)64 * 8 * 128 * 1152];

__device__ __forceinline__ void mma16816(float* c, const uint32_t* a,
                                         const uint32_t* b) {
    asm volatile(
        "mma.sync.aligned.m16n8k16.row.col.f32.bf16.bf16.f32 "
        "{%0,%1,%2,%3}, {%4,%5,%6,%7}, {%8,%9}, {%0,%1,%2,%3};"
        : "+f"(c[0]), "+f"(c[1]), "+f"(c[2]), "+f"(c[3])
        : "r"(a[0]), "r"(a[1]), "r"(a[2]), "r"(a[3]), "r"(b[0]), "r"(b[1]));
}

__device__ __forceinline__ void split2(float x, float y, uint32_t& hi, uint32_t& lo) {
    __nv_bfloat16 hx = __float2bfloat16(x);
    __nv_bfloat16 hy = __float2bfloat16(y);
    __nv_bfloat16 lx = __float2bfloat16(x - __bfloat162float(hx));
    __nv_bfloat16 ly = __float2bfloat16(y - __bfloat162float(hy));
    hi = ((uint32_t)__bfloat16_as_ushort(hy) << 16) | __bfloat16_as_ushort(hx);
    lo = ((uint32_t)__bfloat16_as_ushort(ly) << 16) | __bfloat16_as_ushort(lx);
}

__device__ __forceinline__ int a_slot(int row, int k) {
    const int kstep = k >> 4, kk = k & 15;
    const int mt = row >> 4, rit = row & 15;
    const int lane = ((rit & 7) << 2) | ((kk >> 1) & 3);
    const int r = (rit >> 3) | (((kk >> 3) & 1) << 1);
    return (((kstep << 3) + mt) << 7) + (lane << 2) + r;
}
__device__ __forceinline__ int b_slotN(int n, int k, int NT) {
    const int kstep = k >> 4, kk = k & 15;
    const int nt = n >> 3, gc = n & 7;
    const int lane = (gc << 2) | ((kk >> 1) & 3);
    const int r = (kk >> 3) & 1;
    return (((kstep * NT) + nt) << 6) + (lane << 1) + r;
}

// branches 0..2 = conv_a(query/key/value -> plane), branch 3 = conv_rq(query)
__global__ void __launch_bounds__(256) conv_qkv_kernel(
    const float* __restrict__ query, const float* __restrict__ key,
    const float* __restrict__ value)
{
    const int branch = blockIdx.y;
    const uint32_t o = blockIdx.x * 256 + threadIdx.x;

    if (branch < 3) {
        const float* src = (branch == 0) ? query : (branch == 1) ? key : value;
        const uint32_t region = o >> 10;
        const uint32_t rb = region >> 6, ks = region & 63;
        const uint32_t ol = o & 1023;
        const uint32_t mt = ol >> 7;
        const uint32_t lane = (ol >> 2) & 31;
        const uint32_t r = ol & 3;
        const uint32_t rit = ((r & 1) << 3) | (lane >> 2);
        const uint32_t kk = ((r >> 1) << 3) | ((lane & 3) << 1);
        const uint32_t row = (rb << 7) + (mt << 4) + rit;
        const uint32_t k = (ks << 4) + kk;
        const float2 v = *(const float2*)(src + (size_t)row * 1024 + k);
        uint32_t hi, lo;
        split2(v.x, v.y, hi, lo);
        g_Ah[branch][o] = hi;
        g_Al[branch][o] = lo;
    } else {
        const uint32_t region = o >> 10;
        const uint32_t bhqt = region >> 2, ks = region & 3;
        const uint32_t bh = bhqt >> 3, qt = bhqt & 7;
        const uint32_t b = bh >> 4, h = bh & 15;
        const uint32_t ol = o & 1023;
        const uint32_t mt = ol >> 7;
        const uint32_t lane = (ol >> 2) & 31;
        const uint32_t r = ol & 3;
        const uint32_t rit = ((r & 1) << 3) | (lane >> 2);
        const uint32_t kk = ((r >> 1) << 3) | ((lane & 3) << 1);
        const uint32_t row = (qt << 7) + (mt << 4) + rit;
        const uint32_t k = (ks << 4) + kk;
        const float2 v = *(const float2*)(query + ((size_t)(b * 1024 + row)) * 1024 +
                                          h * 64 + k);
        uint32_t hi, lo;
        split2(v.x, v.y, hi, lo);
        g_RQh[o] = hi;
        g_RQl[o] = lo;
    }
}

__global__ void __launch_bounds__(256) conv_b_all_kernel(
    const float* __restrict__ qw, const float* __restrict__ kw,
    const float* __restrict__ vw)
{
    const int plane = blockIdx.y;
    const float* w = (plane == 0) ? qw : (plane == 1) ? kw : vw;
    const uint32_t o = blockIdx.x * 256 + threadIdx.x;
    const uint32_t region = o >> 10;
    const uint32_t nb = region >> 6, ks = region & 63;
    const uint32_t ol = o & 1023;
    const uint32_t nt = ol >> 6;
    const uint32_t lane = (ol >> 1) & 31;
    const uint32_t r = ol & 1;
    const uint32_t gc = lane >> 2;
    const uint32_t kk = (r << 3) | ((lane & 3) << 1);
    const uint32_t n = (nb << 7) + (nt << 3) + gc;
    const uint32_t k = (ks << 4) + kk;
    const float2 v = *(const float2*)(w + (size_t)n * 1024 + k);
    uint32_t hi, lo;
    split2(v.x, v.y, hi, lo);
    g_Wh[plane][o] = hi;
    g_Wl[plane][o] = lo;
}

__global__ void __launch_bounds__(256) conv_a_kernel(const float* __restrict__ ext,
                                                     int srcsel, int plane)
{
    const float* src = srcsel ? g_O : ext;
    const uint32_t o = blockIdx.x * 256 + threadIdx.x;
    const uint32_t region = o >> 10;
    const uint32_t rb = region >> 6, ks = region & 63;
    const uint32_t ol = o & 1023;
    const uint32_t mt = ol >> 7;
    const uint32_t lane = (ol >> 2) & 31;
    const uint32_t r = ol & 3;
    const uint32_t rit = ((r & 1) << 3) | (lane >> 2);
    const uint32_t kk = ((r >> 1) << 3) | ((lane & 3) << 1);
    const uint32_t row = (rb << 7) + (mt << 4) + rit;
    const uint32_t k = (ks << 4) + kk;
    const float2 v = *(const float2*)(src + (size_t)row * 1024 + k);
    uint32_t hi, lo;
    split2(v.x, v.y, hi, lo);
    g_Ah[plane][o] = hi;
    g_Al[plane][o] = lo;
}

__global__ void __launch_bounds__(256) conv_b_kernel(const float* __restrict__ w,
                                                     int plane)
{
    const uint32_t o = blockIdx.x * 256 + threadIdx.x;
    const uint32_t region = o >> 10;
    const uint32_t nb = region >> 6, ks = region & 63;
    const uint32_t ol = o & 1023;
    const uint32_t nt = ol >> 6;
    const uint32_t lane = (ol >> 1) & 31;
    const uint32_t r = ol & 1;
    const uint32_t gc = lane >> 2;
    const uint32_t kk = (r << 3) | ((lane & 3) << 1);
    const uint32_t n = (nb << 7) + (nt << 3) + gc;
    const uint32_t k = (ks << 4) + kk;
    const float2 v = *(const float2*)(w + (size_t)n * 1024 + k);
    uint32_t hi, lo;
    split2(v.x, v.y, hi, lo);
    g_Wh[plane][o] = hi;
    g_Wl[plane][o] = lo;
}

__global__ void __launch_bounds__(256) conv_v_kernel()
{
    const uint32_t o = blockIdx.x * 256 + threadIdx.x;
    const uint32_t region = o >> 12;
    const uint32_t bh = region >> 3, kt = region & 7;
    const uint32_t ol = o & 4095;
    const uint32_t ks = ol >> 9;
    const uint32_t nt = (ol >> 6) & 7;
    const uint32_t lane = (ol >> 1) & 31;
    const uint32_t r = ol & 1;
    const uint32_t d = (nt << 3) + (lane >> 2);
    const uint32_t key = (ks << 4) + ((r << 3) | ((lane & 3) << 1));
    const size_t vb = ((size_t)bh * 1024 + (kt << 7) + key) * 64 + d;
    const float v0 = g_V[vb];
    const float v1 = g_V[vb + 64];
    uint32_t hi, lo;
    split2(v0, v1, hi, lo);
    g_Vfh[o] = hi;
    g_Vfl[o] = lo;
}

__global__ void __launch_bounds__(256) conv_e_kernel(const float* __restrict__ relE)
{
    const uint32_t o = blockIdx.x * 256 + threadIdx.x;
    const uint32_t qt = o / 36864;
    const uint32_t rem = o - qt * 36864;
    const uint32_t region = rem >> 10;
    const uint32_t nb = region >> 2, ks = region & 3;
    const uint32_t ol = rem & 1023;
    const uint32_t nt = ol >> 6;
    const uint32_t lane = (ol >> 1) & 31;
    const uint32_t r = ol & 1;
    const uint32_t gc = lane >> 2;
    const uint32_t kk = (r << 3) | ((lane & 3) << 1);
    const uint32_t n = (nb << 7) + (nt << 3) + gc;
    const uint32_t k = (ks << 4) + kk;
    int j = 872 - (int)(qt << 7) + (int)n;
    j = j < 0 ? 0 : (j > 1998 ? 1998 : j);
    const float2 v = *(const float2*)(relE + (size_t)j * 64 + k);
    uint32_t hi, lo;
    split2(v.x, v.y, hi, lo);
    g_Eh[o] = hi;
    g_El[o] = lo;
}

__device__ __forceinline__ void gemm_frag_body(
    const float* __restrict__ bias, float* extDst, int dstsel, int plane,
    int nb, int rb)
{
    const int tid = threadIdx.x;
    const int wid = tid >> 5;
    const int lane = tid & 31;
    const int wm = wid >> 2;
    const int wn = wid & 3;
    const int g = lane >> 2;
    const int tig = lane & 3;

    const uint32_t* __restrict__ Ahp = g_Ah[plane];
    const uint32_t* __restrict__ Alp = g_Al[plane];
    const uint32_t* __restrict__ Whp = g_Wh[plane];
    const uint32_t* __restrict__ Wlp = g_Wl[plane];

    float acc[4][4][4];
#pragma unroll
    for (int i = 0; i < 4; i++)
#pragma unroll
        for (int j = 0; j < 4; j++)
#pragma unroll
            for (int r = 0; r < 4; r++) acc[i][j][r] = 0.f;

#pragma unroll 1
    for (int ks = 0; ks < 64; ks++) {
        const size_t abase = (size_t)((((rb << 6) + ks) << 3) + (wm << 2)) * 128 +
                             (lane << 2);
        const size_t bbase = (size_t)((((nb << 6) + ks) << 4) + (wn << 2)) * 64 +
                             (lane << 1);
        uint4 ah[4], al[4];
        uint2 bh[4], bl[4];
#pragma unroll
        for (int i = 0; i < 4; i++) {
            ah[i] = *(const uint4*)(Ahp + abase + (i << 7));
            al[i] = *(const uint4*)(Alp + abase + (i << 7));
        }
#pragma unroll
        for (int j = 0; j < 4; j++) {
            bh[j] = *(const uint2*)(Whp + bbase + (j << 6));
            bl[j] = *(const uint2*)(Wlp + bbase + (j << 6));
        }
#pragma unroll
        for (int i = 0; i < 4; i++)
#pragma unroll
            for (int j = 0; j < 4; j++) {
                mma16816(acc[i][j], (const uint32_t*)&ah[i], (const uint32_t*)&bh[j]);
                mma16816(acc[i][j], (const uint32_t*)&ah[i], (const uint32_t*)&bl[j]);
                mma16816(acc[i][j], (const uint32_t*)&al[i], (const uint32_t*)&bh[j]);
            }
    }

    const int bm = rb << 7;
    const int bn = nb << 7;
#pragma unroll
    for (int i = 0; i < 4; i++) {
        const int m0 = bm + (wm << 6) + (i << 4) + g;
#pragma unroll
        for (int j = 0; j < 4; j++) {
            const int n = bn + (wn << 5) + (j << 3) + (tig << 1);
            const float2 bv = *(const float2*)(bias + n);
#pragma unroll
            for (int half = 0; half < 2; half++) {
                const int m = m0 + (half << 3);
                float2 o;
                o.x = acc[i][j][half * 2 + 0] + bv.x;
                o.y = acc[i][j][half * 2 + 1] + bv.y;
                if (dstsel <= 1) {
                    const int bh2 = ((m >> 10) << 4) + (n >> 6);
                    const int tile = (m >> 7) & 7;
                    const int row = m & 127;
                    const int d = n & 63;
                    uint32_t hi, lo;
                    split2(o.x, o.y, hi, lo);
                    const size_t base = ((size_t)((bh2 << 3) + tile)) << 12;
                    if (dstsel == 0) {
                        const size_t s = base + a_slot(row, d);
                        g_Qfh[s] = hi; g_Qfl[s] = lo;
                    } else {
                        const size_t s = base + b_slotN(row, d, 16);
                        g_Kfh[s] = hi; g_Kfl[s] = lo;
                    }
                } else if (dstsel == 2) {
                    const size_t idx = (((size_t)((m >> 10) * 16 + (n >> 6)) * 1024 +
                                        (size_t)(m & 1023)) << 6) + (n & 63);
                    *(float2*)(g_V + idx) = o;
                } else {
                    *(float2*)(extDst + (size_t)m * 1024 + n) = o;
                }
            }
        }
    }
}

__global__ void __launch_bounds__(256, 2) gemm_frag_all_kernel(
    const float* __restrict__ qb, const float* __restrict__ kb,
    const float* __restrict__ vb)
{
    const int branch = blockIdx.z;
    const float* bias = (branch == 0) ? qb : (branch == 1) ? kb : vb;
    gemm_frag_body(bias, nullptr, branch, branch, blockIdx.x, blockIdx.y);
}

__global__ void __launch_bounds__(256, 2) gemm_frag_kernel(
    const float* __restrict__ bias, float* extDst, int dstsel, int plane)
{
    gemm_frag_body(bias, extDst, dstsel, plane, blockIdx.x, blockIdx.y);
}

__global__ void __launch_bounds__(256, 2) g_gemm_kernel()
{
    const int tid = threadIdx.x;
    const int wid = tid >> 5;
    const int lane = tid & 31;
    const int wm = wid >> 2;
    const int wn = wid & 3;
    const int g = lane >> 2;
    const int tig = lane & 3;
    const int nb = blockIdx.x;
    const int qt = blockIdx.y;
    const int bh = blockIdx.z;

    float acc[4][4][4];
#pragma unroll
    for (int i = 0; i < 4; i++)
#pragma unroll
        for (int j = 0; j < 4; j++)
#pragma unroll
            for (int r = 0; r < 4; r++) acc[i][j][r] = 0.f;

#pragma unroll
    for (int ks = 0; ks < 4; ks++) {
        const size_t abase = (size_t)(((((bh << 3) + qt) << 2) + ks) * 8 +
                                      (wm << 2)) * 128 + (lane << 2);
        const size_t bbase = (size_t)((((qt * 9 + nb) << 2) + ks) * 16 +
                                      (wn << 2)) * 64 + (lane << 1);
        uint4 ah[4], al[4];
        uint2 bh2[4], bl2[4];
#pragma unroll
        for (int i = 0; i < 4; i++) {
            ah[i] = *(const uint4*)(g_RQh + abase + (i << 7));
            al[i] = *(const uint4*)(g_RQl + abase + (i << 7));
        }
#pragma unroll
        for (int j = 0; j < 4; j++) {
            bh2[j] = *(const uint2*)(g_Eh + bbase + (j << 6));
            bl2[j] = *(const uint2*)(g_El + bbase + (j << 6));
        }
#pragma unroll
        for (int i = 0; i < 4; i++)
#pragma unroll
            for (int j = 0; j < 4; j++) {
                mma16816(acc[i][j], (const uint32_t*)&ah[i], (const uint32_t*)&bh2[j]);
                mma16816(acc[i][j], (const uint32_t*)&ah[i], (const uint32_t*)&bl2[j]);
                mma16816(acc[i][j], (const uint32_t*)&al[i], (const uint32_t*)&bh2[j]);
            }
    }

    float* Gb = g_G + (size_t)(((bh << 3) + qt) << 7) * 1152;
#pragma unroll
    for (int i = 0; i < 4; i++) {
        const int m0 = (wm << 6) + (i << 4) + g;
#pragma unroll
        for (int j = 0; j < 4; j++) {
            const int n = (nb << 7) + (wn << 5) + (j << 3) + (tig << 1);
#pragma unroll
            for (int half = 0; half < 2; half++) {
                const int m = m0 + (half << 3);
                *(float2*)(Gb + (size_t)m * 1152 + n) =
                    make_float2(acc[i][j][half * 2 + 0], acc[i][j][half * 2 + 1]);
            }
        }
    }
}

__global__ void mask_detect_kernel(const unsigned int* __restrict__ m) {
    unsigned f = 0;
    for (unsigned i = blockIdx.x * blockDim.x + threadIdx.x; i < (1u << 20);
         i += blockDim.x * gridDim.x) {
        unsigned w = m[i];
        if (w == 0u) continue;
        unsigned lo = w & 0xFFFFu;
        if (lo == 0x3F80u || lo == 0x3C00u) f |= 1u;
        if (((w & 0xFEFEFEFEu) == 0u) && w > 1u) f |= 2u;
    }
    if (f) atomicOr(&g_mask_flags, (int)f);
}

#define QK_SMEM_BYTES 67584

__global__ void __launch_bounds__(256, 1) qk_frag_kernel()
{
    extern __shared__ __align__(16) uint32_t sm[];
    uint32_t* Ksh = sm;
    uint32_t* Ksl = sm + 4096;
    const int tid = threadIdx.x;
    const int wid = tid >> 5;
    const int lane = tid & 31;
    const int g = lane >> 2;
    const int tig = lane & 3;
    const int kt = blockIdx.x, qt = blockIdx.y, bh = blockIdx.z;

    uint4 qh[4], ql[4];
    const size_t qbase = ((size_t)((bh << 3) + qt)) << 12;
#pragma unroll
    for (int s = 0; s < 4; s++) {
        const size_t ai = qbase + (((s << 3) + wid) << 7) + (lane << 2);
        qh[s] = *(const uint4*)(g_Qfh + ai);
        ql[s] = *(const uint4*)(g_Qfl + ai);
    }

    const size_t kbase = ((size_t)((bh << 3) + kt)) << 12;
#pragma unroll
    for (int i = 0; i < 4; i++) {
        const int idx = tid + (i << 8);
        ((uint4*)Ksh)[idx] = *(const uint4*)(g_Kfh + kbase + ((size_t)idx << 2));
        ((uint4*)Ksl)[idx] = *(const uint4*)(g_Kfl + kbase + ((size_t)idx << 2));
    }
    __syncthreads();

    float acc[16][4];
#pragma unroll
    for (int j = 0; j < 16; j++)
#pragma unroll
        for (int r = 0; r < 4; r++) acc[j][r] = 0.f;

#pragma unroll
    for (int j = 0; j < 16; j++) {
#pragma unroll
        for (int s = 0; s < 4; s++) {
            const int bi = (((s << 4) + j) << 6) + (lane << 1);
            uint2 kh2 = *(const uint2*)(Ksh + bi);
            uint2 kl2 = *(const uint2*)(Ksl + bi);
            mma16816(acc[j], (const uint32_t*)&qh[s], (const uint32_t*)&kh2);
            mma16816(acc[j], (const uint32_t*)&qh[s], (const uint32_t*)&kl2);
            mma16816(acc[j], (const uint32_t*)&ql[s], (const uint32_t*)&kh2);
        }
    }
    __syncthreads();

    float* stg = (float*)sm;
    {
        const int r0 = (wid << 4) + g;
#pragma unroll
        for (int j = 0; j < 16; j++) {
            const int col = (j << 3) + (tig << 1);
            *(float2*)&stg[r0 * 132 + col] = make_float2(acc[j][0], acc[j][1]);
            *(float2*)&stg[(r0 + 8) * 132 + col] = make_float2(acc[j][2], acc[j][3]);
        }
    }
    __syncthreads();

    float* Sb = g_S + ((size_t)bh << 20) + ((size_t)(qt << 7)) * 1024 + (kt << 7);
#pragma unroll
    for (int i = 0; i < 16; i++) {
        const int fi = tid + (i << 8);
        const int row = fi >> 5;
        const int c4 = (fi & 31) << 2;
        *(float4*)(Sb + (size_t)row * 1024 + c4) = *(const float4*)&stg[row * 132 + c4];
    }
}

__global__ void __launch_bounds__(256) softmax_kernel(const void* __restrict__ mask)
{
    const int row = blockIdx.x;
    const int q = row & 1023;
    const int bh = row >> 10;
    const int b = bh >> 4;
    float* Srow = g_S + (size_t)row * 1024;
    const size_t mb = ((size_t)(b << 10) + q) * 1024;
    const int tx = threadIdx.x;
    const int k = tx << 2;

    const int fl = g_mask_flags;
    const int wdt = (fl & 1) ? 2 : ((fl & 2) ? 1 : 4);

    const int qi = q & 127;
    const int qt = q >> 7;
    const float* Gp = g_G + ((size_t)(((bh << 3) + qt) << 7) + qi) * 1152 +
                      (127 - qi) + k;

    float4 sv = *(const float4*)(Srow + k);
    float v[4];
    v[0] = (sv.x + Gp[0]) * 8.0f;
    v[1] = (sv.y + Gp[1]) * 8.0f;
    v[2] = (sv.z + Gp[2]) * 8.0f;
    v[3] = (sv.w + Gp[3]) * 8.0f;
    const float NEG = __int_as_float(0xff800000);

    if (wdt == 4) {
        const unsigned int* mp = (const unsigned int*)mask + mb + k;
#pragma unroll
        for (int i = 0; i < 4; i++) if (mp[i]) v[i] = NEG;
    } else if (wdt == 2) {
        const unsigned short* mp = (const unsigned short*)mask + mb + k;
#pragma unroll
        for (int i = 0; i < 4; i++) if (mp[i]) v[i] = NEG;
    } else {
        const unsigned char* mp = (const unsigned char*)mask + mb + k;
#pragma unroll
        for (int i = 0; i < 4; i++) if (mp[i]) v[i] = NEG;
    }

    float mx = fmaxf(fmaxf(v[0], v[1]), fmaxf(v[2], v[3]));
#pragma unroll
    for (int off = 16; off; off >>= 1)
        mx = fmaxf(mx, __shfl_xor_sync(0xffffffffu, mx, off));
    __shared__ float red[8];
    if ((tx & 31) == 0) red[tx >> 5] = mx;
    __syncthreads();
    float rmax = red[0];
#pragma unroll
    for (int i = 1; i < 8; i++) rmax = fmaxf(rmax, red[i]);

    float e[4], s = 0.f;
#pragma unroll
    for (int i = 0; i < 4; i++) { e[i] = expf(v[i] - rmax); s += e[i]; }
#pragma unroll
    for (int off = 16; off; off >>= 1)
        s += __shfl_xor_sync(0xffffffffu, s, off);
    __syncthreads();
    if ((tx & 31) == 0) red[tx >> 5] = s;
    __syncthreads();
    float rs = 0.f;
#pragma unroll
    for (int i = 0; i < 8; i++) rs += red[i];
    const float inv = 1.0f / rs;

    const size_t pbase = ((size_t)((((bh << 3) + qt) << 3) + (k >> 7))) << 13;
    const int kl = k & 127;
    uint32_t hi0, lo0, hi1, lo1;
    split2(e[0] * inv, e[1] * inv, hi0, lo0);
    split2(e[2] * inv, e[3] * inv, hi1, lo1);
    const size_t s0 = pbase + a_slot(qi, kl);
    const size_t s1 = pbase + a_slot(qi, kl + 2);
    g_Pfh[s0] = hi0; g_Pfl[s0] = lo0;
    g_Pfh[s1] = hi1; g_Pfl[s1] = lo1;
}

__global__ void __launch_bounds__(256, 2) av_frag_kernel()
{
    __shared__ __align__(16) uint32_t Vsh[4096];
    __shared__ __align__(16) uint32_t Vsl[4096];
    const int tid = threadIdx.x;
    const int wid = tid >> 5;
    const int lane = tid & 31;
    const int g = lane >> 2;
    const int tig = lane & 3;
    const int qt = blockIdx.x;
    const int bh = blockIdx.y;
    const int b = bh >> 4, h = bh & 15;

    float o[8][4];
#pragma unroll
    for (int j = 0; j < 8; j++)
#pragma unroll
        for (int r = 0; r < 4; r++) o[j][r] = 0.f;

#pragma unroll 1
    for (int kc = 0; kc < 8; kc++) {
        if (kc) __syncthreads();
        const size_t vbase = ((size_t)((bh << 3) + kc)) << 12;
#pragma unroll
        for (int i = 0; i < 4; i++) {
            const int idx = tid + (i << 8);
            ((uint4*)Vsh)[idx] = *(const uint4*)(g_Vfh + vbase + ((size_t)idx << 2));
            ((uint4*)Vsl)[idx] = *(const uint4*)(g_Vfl + vbase + ((size_t)idx << 2));
        }
        __syncthreads();

        const size_t pbase = ((size_t)((((bh << 3) + qt) << 3) + kc)) << 13;
#pragma unroll
        for (int s = 0; s < 8; s++) {
            const size_t ai = pbase + (((s << 3) + wid) << 7) + (lane << 2);
            uint4 ph = *(const uint4*)(g_Pfh + ai);
            uint4 pl = *(const uint4*)(g_Pfl + ai);
#pragma unroll
            for (int j = 0; j < 8; j++) {
                const int bi = (((s << 3) + j) << 6) + (lane << 1);
                uint2 vh = *(const uint2*)(Vsh + bi);
                uint2 vl = *(const uint2*)(Vsl + bi);
                mma16816(o[j], (const uint32_t*)&ph, (const uint32_t*)&vh);
                mma16816(o[j], (const uint32_t*)&ph, (const uint32_t*)&vl);
                mma16816(o[j], (const uint32_t*)&pl, (const uint32_t*)&vh);
            }
        }
    }

    const int qrow = (qt << 7) + (wid << 4) + g;
#pragma unroll
    for (int j = 0; j < 8; j++) {
        const int d = (j << 3) + (tig << 1);
        float* op = g_O + ((size_t)(b * 1024 + qrow)) * 1024 + h * 64 + d;
        *(float2*)op = make_float2(o[j][0], o[j][1]);
        *(float2*)(op + (size_t)8 * 1024) = make_float2(o[j][2], o[j][3]);
    }
}

extern "C" void kernel_launch(void* const* d_in, const int* in_sizes, int n_in,
                              void* d_out, int out_size)
{
    const float* query = (const float*)d_in[0];
    const float* key_i = (const float*)d_in[1];
    const float* value = (const float*)d_in[2];
    const void*  mask  = d_in[3];
    const float* q_w = (const float*)d_in[4];
    const float* q_b = (const float*)d_in[5];
    const float* k_w = (const float*)d_in[6];
    const float* k_b = (const float*)d_in[7];
    const float* v_w = (const float*)d_in[8];
    const float* v_b = (const float*)d_in[9];
    const float* o_w = (const float*)d_in[10];
    const float* o_b = (const float*)d_in[11];
    const float* relE = (const float*)d_in[12];
    float* out = (float*)d_out;

    static int attr_set = 0;
    if (!attr_set) {
        cudaFuncSetAttribute(qk_frag_kernel,
                             cudaFuncAttributeMaxDynamicSharedMemorySize,
                             QK_SMEM_BYTES);
        attr_set = 1;
    }

    conv_qkv_kernel<<<dim3(8192, 4), 256>>>(query, key_i, value);
    conv_b_all_kernel<<<dim3(2048, 3), 256>>>(q_w, k_w, v_w);
    conv_e_kernel<<<1152, 256>>>(relE);
    mask_detect_kernel<<<256, 256>>>((const unsigned int*)mask);

    gemm_frag_all_kernel<<<dim3(8, 32, 3), 256>>>(q_b, k_b, v_b);
    g_gemm_kernel<<<dim3(9, 8, 64), 256>>>();
    conv_v_kernel<<<8192, 256>>>();

    qk_frag_kernel<<<dim3(8, 8, 64), 256, QK_SMEM_BYTES>>>();
    softmax_kernel<<<65536, 256>>>(mask);
    av_frag_kernel<<<dim3(8, 64), 256>>>();

    conv_a_kernel<<<8192, 256>>>(nullptr, 1, 0);
    conv_b_kernel<<<2048, 256>>>(o_w, 0);
    gemm_frag_kernel<<<dim3(8, 32), 256>>>(o_b, out, 3, 0);
}

// round 14
// speedup vs baseline: 2.0545x; 1.0357x over previous
#include <cuda_runtime.h>
#include <cuda_bf16.h>
#include <cstdint>
#include <cstddef>

#define BB 4
#define TT 1024
#define HH 16
#define DD 64
#define CC 1024
#define MM 4096

__device__ float g_V[(size_t)BB * HH * TT * DD];
__device__ float g_S[(size_t)BB * HH * TT * TT];
__device__ int   g_mask_flags;

// A planes: [0..2] = q/k/v activations; plane 0 reused for attention output
__device__ uint32_t g_Ah[3][(size_t)MM * CC / 2];
__device__ uint32_t g_Al[3][(size_t)MM * CC / 2];
// W planes: 0..3 = q_w/k_w/v_w/o_w
__device__ uint32_t g_Wh[4][(size_t)CC * CC / 2];
__device__ uint32_t g_Wl[4][(size_t)CC * CC / 2];

__device__ uint32_t g_Qfh[(size_t)64 * 8 * 4096];
__device__ uint32_t g_Qfl[(size_t)64 * 8 * 4096];
__device__ uint32_t g_Kfh[(size_t)64 * 8 * 4096];
__device__ uint32_t g_Kfl[(size_t)64 * 8 * 4096];
__device__ uint32_t g_Vfh[(size_t)64 * 8 * 4096];
__device__ uint32_t g_Vfl[(size_t)64 * 8 * 4096];

__device__ uint32_t g_Pfh[(size_t)4096 * 8192];
__device__ uint32_t g_Pfl[(size_t)4096 * 8192];

__device__ uint32_t g_RQh[(size_t)64 * 8 * 4096];
__device__ uint32_t g_RQl[(size_t)64 * 8 * 4096];
__device__ uint32_t g_Eh[(size_t)8 * 9 * 4 * 1024];
__device__ uint32_t g_El[(size_t)8 * 9 * 4 * 1024];
__device__ float    g_G[(size_t)64 * 8 * 128 * 1152];

// ===========================================================================
// helpers (validated R4-R13)
// ===========================================================================
__device__ __forceinline__ void mma16816(float* c, const uint32_t* a,
                                         const uint32_t* b) {
    asm volatile(
        "mma.sync.aligned.m16n8k16.row.col.f32.bf16.bf16.f32 "
        "{%0,%1,%2,%3}, {%4,%5,%6,%7}, {%8,%9}, {%0,%1,%2,%3};"
        : "+f"(c[0]), "+f"(c[1]), "+f"(c[2]), "+f"(c[3])
        : "r"(a[0]), "r"(a[1]), "r"(a[2]), "r"(a[3]), "r"(b[0]), "r"(b[1]));
}

__device__ __forceinline__ void split2(float x, float y, uint32_t& hi, uint32_t& lo) {
    __nv_bfloat16 hx = __float2bfloat16(x);
    __nv_bfloat16 hy = __float2bfloat16(y);
    __nv_bfloat16 lx = __float2bfloat16(x - __bfloat162float(hx));
    __nv_bfloat16 ly = __float2bfloat16(y - __bfloat162float(hy));
    hi = ((uint32_t)__bfloat16_as_ushort(hy) << 16) | __bfloat16_as_ushort(hx);
    lo = ((uint32_t)__bfloat16_as_ushort(ly) << 16) | __bfloat16_as_ushort(lx);
}

__device__ __forceinline__ int a_slot(int row, int k) {
    const int kstep = k >> 4, kk = k & 15;
    const int mt = row >> 4, rit = row & 15;
    const int lane = ((rit & 7) << 2) | ((kk >> 1) & 3);
    const int r = (rit >> 3) | (((kk >> 3) & 1) << 1);
    return (((kstep << 3) + mt) << 7) + (lane << 2) + r;
}
__device__ __forceinline__ int b_slotN(int n, int k, int NT) {
    const int kstep = k >> 4, kk = k & 15;
    const int nt = n >> 3, gc = n & 7;
    const int lane = (gc << 2) | ((kk >> 1) & 3);
    const int r = (kk >> 3) & 1;
    return (((kstep * NT) + nt) << 6) + (lane << 1) + r;
}

// ===========================================================================
// conv_all: one launch for every converter + mask detect. grid (8192, 10).
// branches: 0..2 A-planes(q/k/v), 3 RQ, 4 mask detect, 5 E band, 6..9 W planes
// ===========================================================================
__global__ void __launch_bounds__(256) conv_all_kernel(
    const float* __restrict__ query, const float* __restrict__ key,
    const float* __restrict__ value, const void* __restrict__ mask,
    const float* __restrict__ relE,
    const float* __restrict__ qw, const float* __restrict__ kw,
    const float* __restrict__ vw, const float* __restrict__ ow)
{
    const int branch = blockIdx.y;
    const uint32_t o = blockIdx.x * 256 + threadIdx.x;

    if (branch < 3) {
        const float* src = (branch == 0) ? query : (branch == 1) ? key : value;
        const uint32_t region = o >> 10;
        const uint32_t rb = region >> 6, ks = region & 63;
        const uint32_t ol = o & 1023;
        const uint32_t mt = ol >> 7;
        const uint32_t lane = (ol >> 2) & 31;
        const uint32_t r = ol & 3;
        const uint32_t rit = ((r & 1) << 3) | (lane >> 2);
        const uint32_t kk = ((r >> 1) << 3) | ((lane & 3) << 1);
        const uint32_t row = (rb << 7) + (mt << 4) + rit;
        const uint32_t k = (ks << 4) + kk;
        const float2 v = *(const float2*)(src + (size_t)row * 1024 + k);
        uint32_t hi, lo;
        split2(v.x, v.y, hi, lo);
        g_Ah[branch][o] = hi;
        g_Al[branch][o] = lo;
    } else if (branch == 3) {
        const uint32_t region = o >> 10;
        const uint32_t bhqt = region >> 2, ks = region & 3;
        const uint32_t bh = bhqt >> 3, qt = bhqt & 7;
        const uint32_t b = bh >> 4, h = bh & 15;
        const uint32_t ol = o & 1023;
        const uint32_t mt = ol >> 7;
        const uint32_t lane = (ol >> 2) & 31;
        const uint32_t r = ol & 3;
        const uint32_t rit = ((r & 1) << 3) | (lane >> 2);
        const uint32_t kk = ((r >> 1) << 3) | ((lane & 3) << 1);
        const uint32_t row = (qt << 7) + (mt << 4) + rit;
        const uint32_t k = (ks << 4) + kk;
        const float2 v = *(const float2*)(query + ((size_t)(b * 1024 + row)) * 1024 +
                                          h * 64 + k);
        uint32_t hi, lo;
        split2(v.x, v.y, hi, lo);
        g_RQh[o] = hi;
        g_RQl[o] = lo;
    } else if (branch == 4) {
        // mask dtype-width detect: one word per thread over first 4MB
        if (o < (1u << 20)) {
            const unsigned w = ((const unsigned int*)mask)[o];
            if (w != 0u) {
                unsigned f = 0;
                const unsigned lo16 = w & 0xFFFFu;
                if (lo16 == 0x3F80u || lo16 == 0x3C00u) f |= 1u;
                if (((w & 0xFEFEFEFEu) == 0u) && w > 1u) f |= 2u;
                if (f) atomicOr(&g_mask_flags, (int)f);
            }
        }
    } else if (branch == 5) {
        if (o < 294912u) {
            const uint32_t qt = o / 36864;
            const uint32_t rem = o - qt * 36864;
            const uint32_t region = rem >> 10;
            const uint32_t nb = region >> 2, ks = region & 3;
            const uint32_t ol = rem & 1023;
            const uint32_t nt = ol >> 6;
            const uint32_t lane = (ol >> 1) & 31;
            const uint32_t r = ol & 1;
            const uint32_t gc = lane >> 2;
            const uint32_t kk = (r << 3) | ((lane & 3) << 1);
            const uint32_t n = (nb << 7) + (nt << 3) + gc;
            const uint32_t k = (ks << 4) + kk;
            int j = 872 - (int)(qt << 7) + (int)n;
            j = j < 0 ? 0 : (j > 1998 ? 1998 : j);
            const float2 v = *(const float2*)(relE + (size_t)j * 64 + k);
            uint32_t hi, lo;
            split2(v.x, v.y, hi, lo);
            g_Eh[o] = hi;
            g_El[o] = lo;
        }
    } else {
        // branches 6..9: W planes (512K u32 each)
        if (o < (1u << 19)) {
            const int plane = branch - 6;
            const float* w = (plane == 0) ? qw : (plane == 1) ? kw :
                             (plane == 2) ? vw : ow;
            const uint32_t region = o >> 10;
            const uint32_t nb = region >> 6, ks = region & 63;
            const uint32_t ol = o & 1023;
            const uint32_t nt = ol >> 6;
            const uint32_t lane = (ol >> 1) & 31;
            const uint32_t r = ol & 1;
            const uint32_t gc = lane >> 2;
            const uint32_t kk = (r << 3) | ((lane & 3) << 1);
            const uint32_t n = (nb << 7) + (nt << 3) + gc;
            const uint32_t k = (ks << 4) + kk;
            const float2 v = *(const float2*)(w + (size_t)n * 1024 + k);
            uint32_t hi, lo;
            split2(v.x, v.y, hi, lo);
            g_Wh[plane][o] = hi;
            g_Wl[plane][o] = lo;
        }
    }
}

// g_V fp32 head layout -> V fragment planes (validated R8)
__global__ void __launch_bounds__(256) conv_v_kernel()
{
    const uint32_t o = blockIdx.x * 256 + threadIdx.x;
    const uint32_t region = o >> 12;
    const uint32_t bh = region >> 3, kt = region & 7;
    const uint32_t ol = o & 4095;
    const uint32_t ks = ol >> 9;
    const uint32_t nt = (ol >> 6) & 7;
    const uint32_t lane = (ol >> 1) & 31;
    const uint32_t r = ol & 1;
    const uint32_t d = (nt << 3) + (lane >> 2);
    const uint32_t key = (ks << 4) + ((r << 3) | ((lane & 3) << 1));
    const size_t vb = ((size_t)bh * 1024 + (kt << 7) + key) * 64 + d;
    const float v0 = g_V[vb];
    const float v1 = g_V[vb + 64];
    uint32_t hi, lo;
    split2(v0, v1, hi, lo);
    g_Vfh[o] = hi;
    g_Vfl[o] = lo;
}

// ===========================================================================
// projection GEMM body (validated); separate A-plane / W-plane selectors
// dstsel: 0 -> Q planes, 1 -> K planes, 2 -> g_V fp32, 3 -> extDst
// ===========================================================================
__device__ __forceinline__ void gemm_frag_body(
    const float* __restrict__ bias, float* extDst, int dstsel, int aplane,
    int wplane, int nb, int rb)
{
    const int tid = threadIdx.x;
    const int wid = tid >> 5;
    const int lane = tid & 31;
    const int wm = wid >> 2;
    const int wn = wid & 3;
    const int g = lane >> 2;
    const int tig = lane & 3;

    const uint32_t* __restrict__ Ahp = g_Ah[aplane];
    const uint32_t* __restrict__ Alp = g_Al[aplane];
    const uint32_t* __restrict__ Whp = g_Wh[wplane];
    const uint32_t* __restrict__ Wlp = g_Wl[wplane];

    float acc[4][4][4];
#pragma unroll
    for (int i = 0; i < 4; i++)
#pragma unroll
        for (int j = 0; j < 4; j++)
#pragma unroll
            for (int r = 0; r < 4; r++) acc[i][j][r] = 0.f;

#pragma unroll 1
    for (int ks = 0; ks < 64; ks++) {
        const size_t abase = (size_t)((((rb << 6) + ks) << 3) + (wm << 2)) * 128 +
                             (lane << 2);
        const size_t bbase = (size_t)((((nb << 6) + ks) << 4) + (wn << 2)) * 64 +
                             (lane << 1);
        uint4 ah[4], al[4];
        uint2 bh[4], bl[4];
#pragma unroll
        for (int i = 0; i < 4; i++) {
            ah[i] = *(const uint4*)(Ahp + abase + (i << 7));
            al[i] = *(const uint4*)(Alp + abase + (i << 7));
        }
#pragma unroll
        for (int j = 0; j < 4; j++) {
            bh[j] = *(const uint2*)(Whp + bbase + (j << 6));
            bl[j] = *(const uint2*)(Wlp + bbase + (j << 6));
        }
#pragma unroll
        for (int i = 0; i < 4; i++)
#pragma unroll
            for (int j = 0; j < 4; j++) {
                mma16816(acc[i][j], (const uint32_t*)&ah[i], (const uint32_t*)&bh[j]);
                mma16816(acc[i][j], (const uint32_t*)&ah[i], (const uint32_t*)&bl[j]);
                mma16816(acc[i][j], (const uint32_t*)&al[i], (const uint32_t*)&bh[j]);
            }
    }

    const int bm = rb << 7;
    const int bn = nb << 7;
#pragma unroll
    for (int i = 0; i < 4; i++) {
        const int m0 = bm + (wm << 6) + (i << 4) + g;
#pragma unroll
        for (int j = 0; j < 4; j++) {
            const int n = bn + (wn << 5) + (j << 3) + (tig << 1);
            const float2 bv = *(const float2*)(bias + n);
#pragma unroll
            for (int half = 0; half < 2; half++) {
                const int m = m0 + (half << 3);
                float2 o;
                o.x = acc[i][j][half * 2 + 0] + bv.x;
                o.y = acc[i][j][half * 2 + 1] + bv.y;
                if (dstsel <= 1) {
                    const int bh2 = ((m >> 10) << 4) + (n >> 6);
                    const int tile = (m >> 7) & 7;
                    const int row = m & 127;
                    const int d = n & 63;
                    uint32_t hi, lo;
                    split2(o.x, o.y, hi, lo);
                    const size_t base = ((size_t)((bh2 << 3) + tile)) << 12;
                    if (dstsel == 0) {
                        const size_t s = base + a_slot(row, d);
                        g_Qfh[s] = hi; g_Qfl[s] = lo;
                    } else {
                        const size_t s = base + b_slotN(row, d, 16);
                        g_Kfh[s] = hi; g_Kfl[s] = lo;
                    }
                } else if (dstsel == 2) {
                    const size_t idx = (((size_t)((m >> 10) * 16 + (n >> 6)) * 1024 +
                                        (size_t)(m & 1023)) << 6) + (n & 63);
                    *(float2*)(g_V + idx) = o;
                } else {
                    *(float2*)(extDst + (size_t)m * 1024 + n) = o;
                }
            }
        }
    }
}

// G band GEMM body (validated R7-R13)
__device__ __forceinline__ void g_gemm_body(int nb, int qt, int bh)
{
    const int tid = threadIdx.x;
    const int wid = tid >> 5;
    const int lane = tid & 31;
    const int wm = wid >> 2;
    const int wn = wid & 3;
    const int g = lane >> 2;
    const int tig = lane & 3;

    float acc[4][4][4];
#pragma unroll
    for (int i = 0; i < 4; i++)
#pragma unroll
        for (int j = 0; j < 4; j++)
#pragma unroll
            for (int r = 0; r < 4; r++) acc[i][j][r] = 0.f;

#pragma unroll
    for (int ks = 0; ks < 4; ks++) {
        const size_t abase = (size_t)(((((bh << 3) + qt) << 2) + ks) * 8 +
                                      (wm << 2)) * 128 + (lane << 2);
        const size_t bbase = (size_t)((((qt * 9 + nb) << 2) + ks) * 16 +
                                      (wn << 2)) * 64 + (lane << 1);
        uint4 ah[4], al[4];
        uint2 bh2[4], bl2[4];
#pragma unroll
        for (int i = 0; i < 4; i++) {
            ah[i] = *(const uint4*)(g_RQh + abase + (i << 7));
            al[i] = *(const uint4*)(g_RQl + abase + (i << 7));
        }
#pragma unroll
        for (int j = 0; j < 4; j++) {
            bh2[j] = *(const uint2*)(g_Eh + bbase + (j << 6));
            bl2[j] = *(const uint2*)(g_El + bbase + (j << 6));
        }
#pragma unroll
        for (int i = 0; i < 4; i++)
#pragma unroll
            for (int j = 0; j < 4; j++) {
                mma16816(acc[i][j], (const uint32_t*)&ah[i], (const uint32_t*)&bh2[j]);
                mma16816(acc[i][j], (const uint32_t*)&ah[i], (const uint32_t*)&bl2[j]);
                mma16816(acc[i][j], (const uint32_t*)&al[i], (const uint32_t*)&bh2[j]);
            }
    }

    float* Gb = g_G + (size_t)(((bh << 3) + qt) << 7) * 1152;
#pragma unroll
    for (int i = 0; i < 4; i++) {
        const int m0 = (wm << 6) + (i << 4) + g;
#pragma unroll
        for (int j = 0; j < 4; j++) {
            const int n = (nb << 7) + (wn << 5) + (j << 3) + (tig << 1);
#pragma unroll
            for (int half = 0; half < 2; half++) {
                const int m = m0 + (half << 3);
                *(float2*)(Gb + (size_t)m * 1152 + n) =
                    make_float2(acc[i][j][half * 2 + 0], acc[i][j][half * 2 + 1]);
            }
        }
    }
}

// merged Q/K/V projections + G band GEMM: 1D grid 768 + 4608 = 5376
__global__ void __launch_bounds__(256, 2) big_mma_kernel(
    const float* __restrict__ qb, const float* __restrict__ kb,
    const float* __restrict__ vb)
{
    const int bid = blockIdx.x;
    if (bid < 768) {
        const int nb = bid & 7;
        const int rb = (bid >> 3) & 31;
        const int branch = bid >> 8;
        const float* bias = (branch == 0) ? qb : (branch == 1) ? kb : vb;
        gemm_frag_body(bias, nullptr, branch, branch, branch, nb, rb);
    } else {
        const int idx = bid - 768;
        const int nb = idx % 9;
        const int qt = (idx / 9) & 7;
        const int bh = idx / 72;
        g_gemm_body(nb, qt, bh);
    }
}

// output projection: A plane 0 (written by av), W plane 3 (o_w)
__global__ void __launch_bounds__(256, 2) gemm_out_kernel(
    const float* __restrict__ bias, float* extDst)
{
    gemm_frag_body(bias, extDst, 3, 0, 3, blockIdx.x, blockIdx.y);
}

// ===========================================================================
// qk (validated R12/R13)
// ===========================================================================
#define QK_SMEM_BYTES 67584

__global__ void __launch_bounds__(256, 1) qk_frag_kernel()
{
    extern __shared__ __align__(16) uint32_t sm[];
    uint32_t* Ksh = sm;
    uint32_t* Ksl = sm + 4096;
    const int tid = threadIdx.x;
    const int wid = tid >> 5;
    const int lane = tid & 31;
    const int g = lane >> 2;
    const int tig = lane & 3;
    const int kt = blockIdx.x, qt = blockIdx.y, bh = blockIdx.z;

    uint4 qh[4], ql[4];
    const size_t qbase = ((size_t)((bh << 3) + qt)) << 12;
#pragma unroll
    for (int s = 0; s < 4; s++) {
        const size_t ai = qbase + (((s << 3) + wid) << 7) + (lane << 2);
        qh[s] = *(const uint4*)(g_Qfh + ai);
        ql[s] = *(const uint4*)(g_Qfl + ai);
    }

    const size_t kbase = ((size_t)((bh << 3) + kt)) << 12;
#pragma unroll
    for (int i = 0; i < 4; i++) {
        const int idx = tid + (i << 8);
        ((uint4*)Ksh)[idx] = *(const uint4*)(g_Kfh + kbase + ((size_t)idx << 2));
        ((uint4*)Ksl)[idx] = *(const uint4*)(g_Kfl + kbase + ((size_t)idx << 2));
    }
    __syncthreads();

    float acc[16][4];
#pragma unroll
    for (int j = 0; j < 16; j++)
#pragma unroll
        for (int r = 0; r < 4; r++) acc[j][r] = 0.f;

#pragma unroll
    for (int j = 0; j < 16; j++) {
#pragma unroll
        for (int s = 0; s < 4; s++) {
            const int bi = (((s << 4) + j) << 6) + (lane << 1);
            uint2 kh2 = *(const uint2*)(Ksh + bi);
            uint2 kl2 = *(const uint2*)(Ksl + bi);
            mma16816(acc[j], (const uint32_t*)&qh[s], (const uint32_t*)&kh2);
            mma16816(acc[j], (const uint32_t*)&qh[s], (const uint32_t*)&kl2);
            mma16816(acc[j], (const uint32_t*)&ql[s], (const uint32_t*)&kh2);
        }
    }
    __syncthreads();

    float* stg = (float*)sm;
    {
        const int r0 = (wid << 4) + g;
#pragma unroll
        for (int j = 0; j < 16; j++) {
            const int col = (j << 3) + (tig << 1);
            *(float2*)&stg[r0 * 132 + col] = make_float2(acc[j][0], acc[j][1]);
            *(float2*)&stg[(r0 + 8) * 132 + col] = make_float2(acc[j][2], acc[j][3]);
        }
    }
    __syncthreads();

    float* Sb = g_S + ((size_t)bh << 20) + ((size_t)(qt << 7)) * 1024 + (kt << 7);
#pragma unroll
    for (int i = 0; i < 16; i++) {
        const int fi = tid + (i << 8);
        const int row = fi >> 5;
        const int c4 = (fi & 31) << 2;
        *(float4*)(Sb + (size_t)row * 1024 + c4) = *(const float4*)&stg[row * 132 + c4];
    }
}

// ===========================================================================
// fused softmax -> P fragment planes (validated R11-R13)
// ===========================================================================
__global__ void __launch_bounds__(256) softmax_kernel(const void* __restrict__ mask)
{
    const int row = blockIdx.x;
    const int q = row & 1023;
    const int bh = row >> 10;
    const int b = bh >> 4;
    float* Srow = g_S + (size_t)row * 1024;
    const size_t mb = ((size_t)(b << 10) + q) * 1024;
    const int tx = threadIdx.x;
    const int k = tx << 2;

    const int fl = g_mask_flags;
    const int wdt = (fl & 1) ? 2 : ((fl & 2) ? 1 : 4);

    const int qi = q & 127;
    const int qt = q >> 7;
    const float* Gp = g_G + ((size_t)(((bh << 3) + qt) << 7) + qi) * 1152 +
                      (127 - qi) + k;

    float4 sv = *(const float4*)(Srow + k);
    float v[4];
    v[0] = (sv.x + Gp[0]) * 8.0f;
    v[1] = (sv.y + Gp[1]) * 8.0f;
    v[2] = (sv.z + Gp[2]) * 8.0f;
    v[3] = (sv.w + Gp[3]) * 8.0f;
    const float NEG = __int_as_float(0xff800000);

    if (wdt == 4) {
        const unsigned int* mp = (const unsigned int*)mask + mb + k;
#pragma unroll
        for (int i = 0; i < 4; i++) if (mp[i]) v[i] = NEG;
    } else if (wdt == 2) {
        const unsigned short* mp = (const unsigned short*)mask + mb + k;
#pragma unroll
        for (int i = 0; i < 4; i++) if (mp[i]) v[i] = NEG;
    } else {
        const unsigned char* mp = (const unsigned char*)mask + mb + k;
#pragma unroll
        for (int i = 0; i < 4; i++) if (mp[i]) v[i] = NEG;
    }

    float mx = fmaxf(fmaxf(v[0], v[1]), fmaxf(v[2], v[3]));
#pragma unroll
    for (int off = 16; off; off >>= 1)
        mx = fmaxf(mx, __shfl_xor_sync(0xffffffffu, mx, off));
    __shared__ float red[8];
    if ((tx & 31) == 0) red[tx >> 5] = mx;
    __syncthreads();
    float rmax = red[0];
#pragma unroll
    for (int i = 1; i < 8; i++) rmax = fmaxf(rmax, red[i]);

    float e[4], s = 0.f;
#pragma unroll
    for (int i = 0; i < 4; i++) { e[i] = expf(v[i] - rmax); s += e[i]; }
#pragma unroll
    for (int off = 16; off; off >>= 1)
        s += __shfl_xor_sync(0xffffffffu, s, off);
    __syncthreads();
    if ((tx & 31) == 0) red[tx >> 5] = s;
    __syncthreads();
    float rs = 0.f;
#pragma unroll
    for (int i = 0; i < 8; i++) rs += red[i];
    const float inv = 1.0f / rs;

    const size_t pbase = ((size_t)((((bh << 3) + qt) << 3) + (k >> 7))) << 13;
    const int kl = k & 127;
    uint32_t hi0, lo0, hi1, lo1;
    split2(e[0] * inv, e[1] * inv, hi0, lo0);
    split2(e[2] * inv, e[3] * inv, hi1, lo1);
    const size_t s0 = pbase + a_slot(qi, kl);
    const size_t s1 = pbase + a_slot(qi, kl + 2);
    g_Pfh[s0] = hi0; g_Pfl[s0] = lo0;
    g_Pfh[s1] = hi1; g_Pfl[s1] = lo1;
}

// ===========================================================================
// av: P streamed, V staged; epilogue writes output-proj A-planes directly
// ===========================================================================
__global__ void __launch_bounds__(256, 2) av_frag_kernel()
{
    __shared__ __align__(16) uint32_t Vsh[4096];
    __shared__ __align__(16) uint32_t Vsl[4096];
    const int tid = threadIdx.x;
    const int wid = tid >> 5;
    const int lane = tid & 31;
    const int g = lane >> 2;
    const int tig = lane & 3;
    const int qt = blockIdx.x;
    const int bh = blockIdx.y;
    const int b = bh >> 4, h = bh & 15;

    float o[8][4];
#pragma unroll
    for (int j = 0; j < 8; j++)
#pragma unroll
        for (int r = 0; r < 4; r++) o[j][r] = 0.f;

#pragma unroll 1
    for (int kc = 0; kc < 8; kc++) {
        if (kc) __syncthreads();
        const size_t vbase = ((size_t)((bh << 3) + kc)) << 12;
#pragma unroll
        for (int i = 0; i < 4; i++) {
            const int idx = tid + (i << 8);
            ((uint4*)Vsh)[idx] = *(const uint4*)(g_Vfh + vbase + ((size_t)idx << 2));
            ((uint4*)Vsl)[idx] = *(const uint4*)(g_Vfl + vbase + ((size_t)idx << 2));
        }
        __syncthreads();

        const size_t pbase = ((size_t)((((bh << 3) + qt) << 3) + kc)) << 13;
#pragma unroll
        for (int s = 0; s < 8; s++) {
            const size_t ai = pbase + (((s << 3) + wid) << 7) + (lane << 2);
            uint4 ph = *(const uint4*)(g_Pfh + ai);
            uint4 pl = *(const uint4*)(g_Pfl + ai);
#pragma unroll
            for (int j = 0; j < 8; j++) {
                const int bi = (((s << 3) + j) << 6) + (lane << 1);
                uint2 vh = *(const uint2*)(Vsh + bi);
                uint2 vl = *(const uint2*)(Vsl + bi);
                mma16816(o[j], (const uint32_t*)&ph, (const uint32_t*)&vh);
                mma16816(o[j], (const uint32_t*)&ph, (const uint32_t*)&vl);
                mma16816(o[j], (const uint32_t*)&pl, (const uint32_t*)&vh);
            }
        }
    }

    // epilogue: write output rows (m, m+8) cols (n, n+1) into A-plane 0
    const int qrow = (qt << 7) + (wid << 4) + g;
    const int m0 = b * 1024 + qrow;
#pragma unroll
    for (int j = 0; j < 8; j++) {
        const int n = h * 64 + (j << 3) + (tig << 1);
        uint32_t hi, lo;
        split2(o[j][0], o[j][1], hi, lo);
        const size_t s0 = (size_t)(m0 >> 7) * 65536 + a_slot(m0 & 127, n);
        g_Ah[0][s0] = hi; g_Al[0][s0] = lo;
        split2(o[j][2], o[j][3], hi, lo);
        const size_t s1 = (size_t)((m0 + 8) >> 7) * 65536 + a_slot((m0 + 8) & 127, n);
        g_Ah[0][s1] = hi; g_Al[0][s1] = lo;
    }
}

// ===========================================================================
// Launch
// ===========================================================================
extern "C" void kernel_launch(void* const* d_in, const int* in_sizes, int n_in,
                              void* d_out, int out_size)
{
    const float* query = (const float*)d_in[0];
    const float* key_i = (const float*)d_in[1];
    const float* value = (const float*)d_in[2];
    const void*  mask  = d_in[3];
    const float* q_w = (const float*)d_in[4];
    const float* q_b = (const float*)d_in[5];
    const float* k_w = (const float*)d_in[6];
    const float* k_b = (const float*)d_in[7];
    const float* v_w = (const float*)d_in[8];
    const float* v_b = (const float*)d_in[9];
    const float* o_w = (const float*)d_in[10];
    const float* o_b = (const float*)d_in[11];
    const float* relE = (const float*)d_in[12];
    float* out = (float*)d_out;

    static int attr_set = 0;
    if (!attr_set) {
        cudaFuncSetAttribute(qk_frag_kernel,
                             cudaFuncAttributeMaxDynamicSharedMemorySize,
                             QK_SMEM_BYTES);
        attr_set = 1;
    }

    conv_all_kernel<<<dim3(8192, 10), 256>>>(query, key_i, value, mask, relE,
                                             q_w, k_w, v_w, o_w);
    big_mma_kernel<<<5376, 256>>>(q_b, k_b, v_b);
    conv_v_kernel<<<8192, 256>>>();

    qk_frag_kernel<<<dim3(8, 8, 64), 256, QK_SMEM_BYTES>>>();
    softmax_kernel<<<65536, 256>>>(mask);
    av_frag_kernel<<<dim3(8, 64), 256>>>();

    gemm_out_kernel<<<dim3(8, 32), 256>>>(o_b, out);
}

// round 15
// speedup vs baseline: 2.0965x; 1.0204x over previous
#include <cuda_runtime.h>
#include <cuda_bf16.h>
#include <cstdint>
#include <cstddef>

#define BB 4
#define TT 1024
#define HH 16
#define DD 64
#define CC 1024
#define MM 4096

__device__ float g_V[(size_t)BB * HH * TT * DD];
__device__ float g_S[(size_t)BB * HH * TT * TT];
__device__ int   g_mask_flags;

__device__ uint32_t g_Ah[3][(size_t)MM * CC / 2];
__device__ uint32_t g_Al[3][(size_t)MM * CC / 2];
__device__ uint32_t g_Wh[4][(size_t)CC * CC / 2];
__device__ uint32_t g_Wl[4][(size_t)CC * CC / 2];

__device__ uint32_t g_Qfh[(size_t)64 * 8 * 4096];
__device__ uint32_t g_Qfl[(size_t)64 * 8 * 4096];
__device__ uint32_t g_Kfh[(size_t)64 * 8 * 4096];
__device__ uint32_t g_Kfl[(size_t)64 * 8 * 4096];
__device__ uint32_t g_Vfh[(size_t)64 * 8 * 4096];
__device__ uint32_t g_Vfl[(size_t)64 * 8 * 4096];

__device__ uint32_t g_Pfh[(size_t)4096 * 8192];
__device__ uint32_t g_Pfl[(size_t)4096 * 8192];

__device__ uint32_t g_RQh[(size_t)64 * 8 * 4096];
__device__ uint32_t g_RQl[(size_t)64 * 8 * 4096];
__device__ uint32_t g_Eh[(size_t)8 * 9 * 4 * 1024];
__device__ uint32_t g_El[(size_t)8 * 9 * 4 * 1024];
__device__ float    g_G[(size_t)64 * 8 * 128 * 1152];

// ===========================================================================
// helpers (validated R4-R14)
// ===========================================================================
__device__ __forceinline__ void mma16816(float* c, const uint32_t* a,
                                         const uint32_t* b) {
    asm volatile(
        "mma.sync.aligned.m16n8k16.row.col.f32.bf16.bf16.f32 "
        "{%0,%1,%2,%3}, {%4,%5,%6,%7}, {%8,%9}, {%0,%1,%2,%3};"
        : "+f"(c[0]), "+f"(c[1]), "+f"(c[2]), "+f"(c[3])
        : "r"(a[0]), "r"(a[1]), "r"(a[2]), "r"(a[3]), "r"(b[0]), "r"(b[1]));
}

__device__ __forceinline__ void split2(float x, float y, uint32_t& hi, uint32_t& lo) {
    __nv_bfloat16 hx = __float2bfloat16(x);
    __nv_bfloat16 hy = __float2bfloat16(y);
    __nv_bfloat16 lx = __float2bfloat16(x - __bfloat162float(hx));
    __nv_bfloat16 ly = __float2bfloat16(y - __bfloat162float(hy));
    hi = ((uint32_t)__bfloat16_as_ushort(hy) << 16) | __bfloat16_as_ushort(hx);
    lo = ((uint32_t)__bfloat16_as_ushort(ly) << 16) | __bfloat16_as_ushort(lx);
}

__device__ __forceinline__ int a_slot(int row, int k) {
    const int kstep = k >> 4, kk = k & 15;
    const int mt = row >> 4, rit = row & 15;
    const int lane = ((rit & 7) << 2) | ((kk >> 1) & 3);
    const int r = (rit >> 3) | (((kk >> 3) & 1) << 1);
    return (((kstep << 3) + mt) << 7) + (lane << 2) + r;
}
__device__ __forceinline__ int b_slotN(int n, int k, int NT) {
    const int kstep = k >> 4, kk = k & 15;
    const int nt = n >> 3, gc = n & 7;
    const int lane = (gc << 2) | ((kk >> 1) & 3);
    const int r = (kk >> 3) & 1;
    return (((kstep * NT) + nt) << 6) + (lane << 1) + r;
}

// ===========================================================================
// conv_all (validated R14): grid (8192, 10)
// ===========================================================================
__global__ void __launch_bounds__(256) conv_all_kernel(
    const float* __restrict__ query, const float* __restrict__ key,
    const float* __restrict__ value, const void* __restrict__ mask,
    const float* __restrict__ relE,
    const float* __restrict__ qw, const float* __restrict__ kw,
    const float* __restrict__ vw, const float* __restrict__ ow)
{
    const int branch = blockIdx.y;
    const uint32_t o = blockIdx.x * 256 + threadIdx.x;

    if (branch < 3) {
        const float* src = (branch == 0) ? query : (branch == 1) ? key : value;
        const uint32_t region = o >> 10;
        const uint32_t rb = region >> 6, ks = region & 63;
        const uint32_t ol = o & 1023;
        const uint32_t mt = ol >> 7;
        const uint32_t lane = (ol >> 2) & 31;
        const uint32_t r = ol & 3;
        const uint32_t rit = ((r & 1) << 3) | (lane >> 2);
        const uint32_t kk = ((r >> 1) << 3) | ((lane & 3) << 1);
        const uint32_t row = (rb << 7) + (mt << 4) + rit;
        const uint32_t k = (ks << 4) + kk;
        const float2 v = *(const float2*)(src + (size_t)row * 1024 + k);
        uint32_t hi, lo;
        split2(v.x, v.y, hi, lo);
        g_Ah[branch][o] = hi;
        g_Al[branch][o] = lo;
    } else if (branch == 3) {
        const uint32_t region = o >> 10;
        const uint32_t bhqt = region >> 2, ks = region & 3;
        const uint32_t bh = bhqt >> 3, qt = bhqt & 7;
        const uint32_t b = bh >> 4, h = bh & 15;
        const uint32_t ol = o & 1023;
        const uint32_t mt = ol >> 7;
        const uint32_t lane = (ol >> 2) & 31;
        const uint32_t r = ol & 3;
        const uint32_t rit = ((r & 1) << 3) | (lane >> 2);
        const uint32_t kk = ((r >> 1) << 3) | ((lane & 3) << 1);
        const uint32_t row = (qt << 7) + (mt << 4) + rit;
        const uint32_t k = (ks << 4) + kk;
        const float2 v = *(const float2*)(query + ((size_t)(b * 1024 + row)) * 1024 +
                                          h * 64 + k);
        uint32_t hi, lo;
        split2(v.x, v.y, hi, lo);
        g_RQh[o] = hi;
        g_RQl[o] = lo;
    } else if (branch == 4) {
        if (o < (1u << 20)) {
            const unsigned w = ((const unsigned int*)mask)[o];
            if (w != 0u) {
                unsigned f = 0;
                const unsigned lo16 = w & 0xFFFFu;
                if (lo16 == 0x3F80u || lo16 == 0x3C00u) f |= 1u;
                if (((w & 0xFEFEFEFEu) == 0u) && w > 1u) f |= 2u;
                if (f) atomicOr(&g_mask_flags, (int)f);
            }
        }
    } else if (branch == 5) {
        if (o < 294912u) {
            const uint32_t qt = o / 36864;
            const uint32_t rem = o - qt * 36864;
            const uint32_t region = rem >> 10;
            const uint32_t nb = region >> 2, ks = region & 3;
            const uint32_t ol = rem & 1023;
            const uint32_t nt = ol >> 6;
            const uint32_t lane = (ol >> 1) & 31;
            const uint32_t r = ol & 1;
            const uint32_t gc = lane >> 2;
            const uint32_t kk = (r << 3) | ((lane & 3) << 1);
            const uint32_t n = (nb << 7) + (nt << 3) + gc;
            const uint32_t k = (ks << 4) + kk;
            int j = 872 - (int)(qt << 7) + (int)n;
            j = j < 0 ? 0 : (j > 1998 ? 1998 : j);
            const float2 v = *(const float2*)(relE + (size_t)j * 64 + k);
            uint32_t hi, lo;
            split2(v.x, v.y, hi, lo);
            g_Eh[o] = hi;
            g_El[o] = lo;
        }
    } else {
        if (o < (1u << 19)) {
            const int plane = branch - 6;
            const float* w = (plane == 0) ? qw : (plane == 1) ? kw :
                             (plane == 2) ? vw : ow;
            const uint32_t region = o >> 10;
            const uint32_t nb = region >> 6, ks = region & 63;
            const uint32_t ol = o & 1023;
            const uint32_t nt = ol >> 6;
            const uint32_t lane = (ol >> 1) & 31;
            const uint32_t r = ol & 1;
            const uint32_t gc = lane >> 2;
            const uint32_t kk = (r << 3) | ((lane & 3) << 1);
            const uint32_t n = (nb << 7) + (nt << 3) + gc;
            const uint32_t k = (ks << 4) + kk;
            const float2 v = *(const float2*)(w + (size_t)n * 1024 + k);
            uint32_t hi, lo;
            split2(v.x, v.y, hi, lo);
            g_Wh[plane][o] = hi;
            g_Wl[plane][o] = lo;
        }
    }
}

__global__ void __launch_bounds__(256) conv_v_kernel()
{
    const uint32_t o = blockIdx.x * 256 + threadIdx.x;
    const uint32_t region = o >> 12;
    const uint32_t bh = region >> 3, kt = region & 7;
    const uint32_t ol = o & 4095;
    const uint32_t ks = ol >> 9;
    const uint32_t nt = (ol >> 6) & 7;
    const uint32_t lane = (ol >> 1) & 31;
    const uint32_t r = ol & 1;
    const uint32_t d = (nt << 3) + (lane >> 2);
    const uint32_t key = (ks << 4) + ((r << 3) | ((lane & 3) << 1));
    const size_t vb = ((size_t)bh * 1024 + (kt << 7) + key) * 64 + d;
    const float v0 = g_V[vb];
    const float v1 = g_V[vb + 64];
    uint32_t hi, lo;
    split2(v0, v1, hi, lo);
    g_Vfh[o] = hi;
    g_Vfl[o] = lo;
}

// ===========================================================================
// projection GEMM body (validated; ks loop now unroll 2 for load/mma overlap)
// ===========================================================================
__device__ __forceinline__ void gemm_frag_body(
    const float* __restrict__ bias, float* extDst, int dstsel, int aplane,
    int wplane, int nb, int rb)
{
    const int tid = threadIdx.x;
    const int wid = tid >> 5;
    const int lane = tid & 31;
    const int wm = wid >> 2;
    const int wn = wid & 3;
    const int g = lane >> 2;
    const int tig = lane & 3;

    const uint32_t* __restrict__ Ahp = g_Ah[aplane];
    const uint32_t* __restrict__ Alp = g_Al[aplane];
    const uint32_t* __restrict__ Whp = g_Wh[wplane];
    const uint32_t* __restrict__ Wlp = g_Wl[wplane];

    float acc[4][4][4];
#pragma unroll
    for (int i = 0; i < 4; i++)
#pragma unroll
        for (int j = 0; j < 4; j++)
#pragma unroll
            for (int r = 0; r < 4; r++) acc[i][j][r] = 0.f;

#pragma unroll 2
    for (int ks = 0; ks < 64; ks++) {
        const size_t abase = (size_t)((((rb << 6) + ks) << 3) + (wm << 2)) * 128 +
                             (lane << 2);
        const size_t bbase = (size_t)((((nb << 6) + ks) << 4) + (wn << 2)) * 64 +
                             (lane << 1);
        uint4 ah[4], al[4];
        uint2 bh[4], bl[4];
#pragma unroll
        for (int i = 0; i < 4; i++) {
            ah[i] = *(const uint4*)(Ahp + abase + (i << 7));
            al[i] = *(const uint4*)(Alp + abase + (i << 7));
        }
#pragma unroll
        for (int j = 0; j < 4; j++) {
            bh[j] = *(const uint2*)(Whp + bbase + (j << 6));
            bl[j] = *(const uint2*)(Wlp + bbase + (j << 6));
        }
#pragma unroll
        for (int i = 0; i < 4; i++)
#pragma unroll
            for (int j = 0; j < 4; j++) {
                mma16816(acc[i][j], (const uint32_t*)&ah[i], (const uint32_t*)&bh[j]);
                mma16816(acc[i][j], (const uint32_t*)&ah[i], (const uint32_t*)&bl[j]);
                mma16816(acc[i][j], (const uint32_t*)&al[i], (const uint32_t*)&bh[j]);
            }
    }

    const int bm = rb << 7;
    const int bn = nb << 7;
#pragma unroll
    for (int i = 0; i < 4; i++) {
        const int m0 = bm + (wm << 6) + (i << 4) + g;
#pragma unroll
        for (int j = 0; j < 4; j++) {
            const int n = bn + (wn << 5) + (j << 3) + (tig << 1);
            const float2 bv = *(const float2*)(bias + n);
#pragma unroll
            for (int half = 0; half < 2; half++) {
                const int m = m0 + (half << 3);
                float2 o;
                o.x = acc[i][j][half * 2 + 0] + bv.x;
                o.y = acc[i][j][half * 2 + 1] + bv.y;
                if (dstsel <= 1) {
                    const int bh2 = ((m >> 10) << 4) + (n >> 6);
                    const int tile = (m >> 7) & 7;
                    const int row = m & 127;
                    const int d = n & 63;
                    uint32_t hi, lo;
                    split2(o.x, o.y, hi, lo);
                    const size_t base = ((size_t)((bh2 << 3) + tile)) << 12;
                    if (dstsel == 0) {
                        const size_t s = base + a_slot(row, d);
                        g_Qfh[s] = hi; g_Qfl[s] = lo;
                    } else {
                        const size_t s = base + b_slotN(row, d, 16);
                        g_Kfh[s] = hi; g_Kfl[s] = lo;
                    }
                } else if (dstsel == 2) {
                    const size_t idx = (((size_t)((m >> 10) * 16 + (n >> 6)) * 1024 +
                                        (size_t)(m & 1023)) << 6) + (n & 63);
                    *(float2*)(g_V + idx) = o;
                } else {
                    *(float2*)(extDst + (size_t)m * 1024 + n) = o;
                }
            }
        }
    }
}

__device__ __forceinline__ void g_gemm_body(int nb, int qt, int bh)
{
    const int tid = threadIdx.x;
    const int wid = tid >> 5;
    const int lane = tid & 31;
    const int wm = wid >> 2;
    const int wn = wid & 3;
    const int g = lane >> 2;
    const int tig = lane & 3;

    float acc[4][4][4];
#pragma unroll
    for (int i = 0; i < 4; i++)
#pragma unroll
        for (int j = 0; j < 4; j++)
#pragma unroll
            for (int r = 0; r < 4; r++) acc[i][j][r] = 0.f;

#pragma unroll
    for (int ks = 0; ks < 4; ks++) {
        const size_t abase = (size_t)(((((bh << 3) + qt) << 2) + ks) * 8 +
                                      (wm << 2)) * 128 + (lane << 2);
        const size_t bbase = (size_t)((((qt * 9 + nb) << 2) + ks) * 16 +
                                      (wn << 2)) * 64 + (lane << 1);
        uint4 ah[4], al[4];
        uint2 bh2[4], bl2[4];
#pragma unroll
        for (int i = 0; i < 4; i++) {
            ah[i] = *(const uint4*)(g_RQh + abase + (i << 7));
            al[i] = *(const uint4*)(g_RQl + abase + (i << 7));
        }
#pragma unroll
        for (int j = 0; j < 4; j++) {
            bh2[j] = *(const uint2*)(g_Eh + bbase + (j << 6));
            bl2[j] = *(const uint2*)(g_El + bbase + (j << 6));
        }
#pragma unroll
        for (int i = 0; i < 4; i++)
#pragma unroll
            for (int j = 0; j < 4; j++) {
                mma16816(acc[i][j], (const uint32_t*)&ah[i], (const uint32_t*)&bh2[j]);
                mma16816(acc[i][j], (const uint32_t*)&ah[i], (const uint32_t*)&bl2[j]);
                mma16816(acc[i][j], (const uint32_t*)&al[i], (const uint32_t*)&bh2[j]);
            }
    }

    float* Gb = g_G + (size_t)(((bh << 3) + qt) << 7) * 1152;
#pragma unroll
    for (int i = 0; i < 4; i++) {
        const int m0 = (wm << 6) + (i << 4) + g;
#pragma unroll
        for (int j = 0; j < 4; j++) {
            const int n = (nb << 7) + (wn << 5) + (j << 3) + (tig << 1);
#pragma unroll
            for (int half = 0; half < 2; half++) {
                const int m = m0 + (half << 3);
                *(float2*)(Gb + (size_t)m * 1152 + n) =
                    make_float2(acc[i][j][half * 2 + 0], acc[i][j][half * 2 + 1]);
            }
        }
    }
}

__global__ void __launch_bounds__(256, 2) big_mma_kernel(
    const float* __restrict__ qb, const float* __restrict__ kb,
    const float* __restrict__ vb)
{
    const int bid = blockIdx.x;
    if (bid < 768) {
        const int nb = bid & 7;
        const int rb = (bid >> 3) & 31;
        const int branch = bid >> 8;
        const float* bias = (branch == 0) ? qb : (branch == 1) ? kb : vb;
        gemm_frag_body(bias, nullptr, branch, branch, branch, nb, rb);
    } else {
        const int idx = bid - 768;
        const int nb = idx % 9;
        const int qt = (idx / 9) & 7;
        const int bh = idx / 72;
        g_gemm_body(nb, qt, bh);
    }
}

__global__ void __launch_bounds__(256, 2) gemm_out_kernel(
    const float* __restrict__ bias, float* extDst)
{
    gemm_frag_body(bias, extDst, 3, 0, 3, blockIdx.x, blockIdx.y);
}

// ===========================================================================
// qk (validated R12-R14, unchanged)
// ===========================================================================
#define QK_SMEM_BYTES 67584

__global__ void __launch_bounds__(256, 1) qk_frag_kernel()
{
    extern __shared__ __align__(16) uint32_t sm[];
    uint32_t* Ksh = sm;
    uint32_t* Ksl = sm + 4096;
    const int tid = threadIdx.x;
    const int wid = tid >> 5;
    const int lane = tid & 31;
    const int g = lane >> 2;
    const int tig = lane & 3;
    const int kt = blockIdx.x, qt = blockIdx.y, bh = blockIdx.z;

    uint4 qh[4], ql[4];
    const size_t qbase = ((size_t)((bh << 3) + qt)) << 12;
#pragma unroll
    for (int s = 0; s < 4; s++) {
        const size_t ai = qbase + (((s << 3) + wid) << 7) + (lane << 2);
        qh[s] = *(const uint4*)(g_Qfh + ai);
        ql[s] = *(const uint4*)(g_Qfl + ai);
    }

    const size_t kbase = ((size_t)((bh << 3) + kt)) << 12;
#pragma unroll
    for (int i = 0; i < 4; i++) {
        const int idx = tid + (i << 8);
        ((uint4*)Ksh)[idx] = *(const uint4*)(g_Kfh + kbase + ((size_t)idx << 2));
        ((uint4*)Ksl)[idx] = *(const uint4*)(g_Kfl + kbase + ((size_t)idx << 2));
    }
    __syncthreads();

    float acc[16][4];
#pragma unroll
    for (int j = 0; j < 16; j++)
#pragma unroll
        for (int r = 0; r < 4; r++) acc[j][r] = 0.f;

#pragma unroll
    for (int j = 0; j < 16; j++) {
#pragma unroll
        for (int s = 0; s < 4; s++) {
            const int bi = (((s << 4) + j) << 6) + (lane << 1);
            uint2 kh2 = *(const uint2*)(Ksh + bi);
            uint2 kl2 = *(const uint2*)(Ksl + bi);
            mma16816(acc[j], (const uint32_t*)&qh[s], (const uint32_t*)&kh2);
            mma16816(acc[j], (const uint32_t*)&qh[s], (const uint32_t*)&kl2);
            mma16816(acc[j], (const uint32_t*)&ql[s], (const uint32_t*)&kh2);
        }
    }
    __syncthreads();

    float* stg = (float*)sm;
    {
        const int r0 = (wid << 4) + g;
#pragma unroll
        for (int j = 0; j < 16; j++) {
            const int col = (j << 3) + (tig << 1);
            *(float2*)&stg[r0 * 132 + col] = make_float2(acc[j][0], acc[j][1]);
            *(float2*)&stg[(r0 + 8) * 132 + col] = make_float2(acc[j][2], acc[j][3]);
        }
    }
    __syncthreads();

    float* Sb = g_S + ((size_t)bh << 20) + ((size_t)(qt << 7)) * 1024 + (kt << 7);
#pragma unroll
    for (int i = 0; i < 16; i++) {
        const int fi = tid + (i << 8);
        const int row = fi >> 5;
        const int c4 = (fi & 31) << 2;
        *(float4*)(Sb + (size_t)row * 1024 + c4) = *(const float4*)&stg[row * 132 + c4];
    }
}

// ===========================================================================
// warp-per-row softmax: 8 rows/block, shfl-only reductions, no smem/syncs.
// v = (S + G)*8, mask, softmax -> P fragment planes. grid 8192.
// ===========================================================================
__global__ void __launch_bounds__(256) softmax_kernel(const void* __restrict__ mask)
{
    const int wid = threadIdx.x >> 5;
    const int lane = threadIdx.x & 31;
    const int row = blockIdx.x * 8 + wid;
    const int q = row & 1023;
    const int bh = row >> 10;
    const int b = bh >> 4;
    const float* Srow = g_S + (size_t)row * 1024;
    const size_t mb = ((size_t)(b << 10) + q) * 1024;

    const int fl = g_mask_flags;
    const int wdt = (fl & 1) ? 2 : ((fl & 2) ? 1 : 4);

    const int qi = q & 127;
    const int qt = q >> 7;
    const float* Gp = g_G + ((size_t)(((bh << 3) + qt) << 7) + qi) * 1152 +
                      (127 - qi);

    const float NEG = __int_as_float(0xff800000);
    float v[32];

#pragma unroll
    for (int i = 0; i < 8; i++) {
        const int k = (i << 7) + (lane << 2);
        float4 sv = *(const float4*)(Srow + k);
        float* vv = v + (i << 2);
        vv[0] = (sv.x + Gp[k + 0]) * 8.0f;
        vv[1] = (sv.y + Gp[k + 1]) * 8.0f;
        vv[2] = (sv.z + Gp[k + 2]) * 8.0f;
        vv[3] = (sv.w + Gp[k + 3]) * 8.0f;
        if (wdt == 4) {
            const unsigned int* mp = (const unsigned int*)mask + mb + k;
#pragma unroll
            for (int t = 0; t < 4; t++) if (mp[t]) vv[t] = NEG;
        } else if (wdt == 2) {
            const unsigned short* mp = (const unsigned short*)mask + mb + k;
#pragma unroll
            for (int t = 0; t < 4; t++) if (mp[t]) vv[t] = NEG;
        } else {
            const unsigned char* mp = (const unsigned char*)mask + mb + k;
#pragma unroll
            for (int t = 0; t < 4; t++) if (mp[t]) vv[t] = NEG;
        }
    }

    float mx = NEG;
#pragma unroll
    for (int i = 0; i < 32; i++) mx = fmaxf(mx, v[i]);
#pragma unroll
    for (int off = 16; off; off >>= 1)
        mx = fmaxf(mx, __shfl_xor_sync(0xffffffffu, mx, off));

    float s = 0.f;
#pragma unroll
    for (int i = 0; i < 32; i++) { v[i] = expf(v[i] - mx); s += v[i]; }
#pragma unroll
    for (int off = 16; off; off >>= 1)
        s += __shfl_xor_sync(0xffffffffu, s, off);
    const float inv = 1.0f / s;

#pragma unroll
    for (int i = 0; i < 8; i++) {
        const int k = (i << 7) + (lane << 2);
        const size_t pbase = ((size_t)((((bh << 3) + qt) << 3) + (k >> 7))) << 13;
        const int kl = k & 127;
        const float* vv = v + (i << 2);
        uint32_t hi0, lo0, hi1, lo1;
        split2(vv[0] * inv, vv[1] * inv, hi0, lo0);
        split2(vv[2] * inv, vv[3] * inv, hi1, lo1);
        const size_t s0 = pbase + a_slot(qi, kl);
        const size_t s1 = pbase + a_slot(qi, kl + 2);
        g_Pfh[s0] = hi0; g_Pfl[s0] = lo0;
        g_Pfh[s1] = hi1; g_Pfl[s1] = lo1;
    }
}

// ===========================================================================
// av (validated R13/R14): P streamed, V staged; writes output-proj A-planes
// ===========================================================================
__global__ void __launch_bounds__(256, 2) av_frag_kernel()
{
    __shared__ __align__(16) uint32_t Vsh[4096];
    __shared__ __align__(16) uint32_t Vsl[4096];
    const int tid = threadIdx.x;
    const int wid = tid >> 5;
    const int lane = tid & 31;
    const int g = lane >> 2;
    const int tig = lane & 3;
    const int qt = blockIdx.x;
    const int bh = blockIdx.y;
    const int b = bh >> 4, h = bh & 15;

    float o[8][4];
#pragma unroll
    for (int j = 0; j < 8; j++)
#pragma unroll
        for (int r = 0; r < 4; r++) o[j][r] = 0.f;

#pragma unroll 1
    for (int kc = 0; kc < 8; kc++) {
        if (kc) __syncthreads();
        const size_t vbase = ((size_t)((bh << 3) + kc)) << 12;
#pragma unroll
        for (int i = 0; i < 4; i++) {
            const int idx = tid + (i << 8);
            ((uint4*)Vsh)[idx] = *(const uint4*)(g_Vfh + vbase + ((size_t)idx << 2));
            ((uint4*)Vsl)[idx] = *(const uint4*)(g_Vfl + vbase + ((size_t)idx << 2));
        }
        __syncthreads();

        const size_t pbase = ((size_t)((((bh << 3) + qt) << 3) + kc)) << 13;
#pragma unroll
        for (int s = 0; s < 8; s++) {
            const size_t ai = pbase + (((s << 3) + wid) << 7) + (lane << 2);
            uint4 ph = *(const uint4*)(g_Pfh + ai);
            uint4 pl = *(const uint4*)(g_Pfl + ai);
#pragma unroll
            for (int j = 0; j < 8; j++) {
                const int bi = (((s << 3) + j) << 6) + (lane << 1);
                uint2 vh = *(const uint2*)(Vsh + bi);
                uint2 vl = *(const uint2*)(Vsl + bi);
                mma16816(o[j], (const uint32_t*)&ph, (const uint32_t*)&vh);
                mma16816(o[j], (const uint32_t*)&ph, (const uint32_t*)&vl);
                mma16816(o[j], (const uint32_t*)&pl, (const uint32_t*)&vh);
            }
        }
    }

    const int qrow = (qt << 7) + (wid << 4) + g;
    const int m0 = b * 1024 + qrow;
#pragma unroll
    for (int j = 0; j < 8; j++) {
        const int n = h * 64 + (j << 3) + (tig << 1);
        uint32_t hi, lo;
        split2(o[j][0], o[j][1], hi, lo);
        const size_t s0 = (size_t)(m0 >> 7) * 65536 + a_slot(m0 & 127, n);
        g_Ah[0][s0] = hi; g_Al[0][s0] = lo;
        split2(o[j][2], o[j][3], hi, lo);
        const size_t s1 = (size_t)((m0 + 8) >> 7) * 65536 + a_slot((m0 + 8) & 127, n);
        g_Ah[0][s1] = hi; g_Al[0][s1] = lo;
    }
}

// ===========================================================================
// Launch
// ===========================================================================
extern "C" void kernel_launch(void* const* d_in, const int* in_sizes, int n_in,
                              void* d_out, int out_size)
{
    const float* query = (const float*)d_in[0];
    const float* key_i = (const float*)d_in[1];
    const float* value = (const float*)d_in[2];
    const void*  mask  = d_in[3];
    const float* q_w = (const float*)d_in[4];
    const float* q_b = (const float*)d_in[5];
    const float* k_w = (const float*)d_in[6];
    const float* k_b = (const float*)d_in[7];
    const float* v_w = (const float*)d_in[8];
    const float* v_b = (const float*)d_in[9];
    const float* o_w = (const float*)d_in[10];
    const float* o_b = (const float*)d_in[11];
    const float* relE = (const float*)d_in[12];
    float* out = (float*)d_out;

    static int attr_set = 0;
    if (!attr_set) {
        cudaFuncSetAttribute(qk_frag_kernel,
                             cudaFuncAttributeMaxDynamicSharedMemorySize,
                             QK_SMEM_BYTES);
        attr_set = 1;
    }

    conv_all_kernel<<<dim3(8192, 10), 256>>>(query, key_i, value, mask, relE,
                                             q_w, k_w, v_w, o_w);
    big_mma_kernel<<<5376, 256>>>(q_b, k_b, v_b);
    conv_v_kernel<<<8192, 256>>>();

    qk_frag_kernel<<<dim3(8, 8, 64), 256, QK_SMEM_BYTES>>>();
    softmax_kernel<<<8192, 256>>>(mask);
    av_frag_kernel<<<dim3(8, 64), 256>>>();

    gemm_out_kernel<<<dim3(8, 32), 256>>>(o_b, out);
}